// round 4
// baseline (speedup 1.0000x reference)
#include <cuda_runtime.h>
#include <cuda_bf16.h>
#include <math.h>
#include <stdint.h>

// ---------------- problem constants ----------------
#define NNODE   20000
#define NPAD    20096          // multiple of 128
#define EDGES   640000
#define BB      256
#define DG      256
#define DH      512
#define DI      2048
#define RNK     512
#define NCLS    3
#define NGENE   6640
#define LN_EPS  1e-5f

// ---------------- scratch (device globals) ----------------
__device__ float g_x   [NPAD * DG];
__device__ float g_hln [NPAD * DG];
__device__ float g_agg [NPAD * DG];
__device__ int   g_deg [NNODE];
__device__ int   g_off [NNODE + 1];
__device__ int   g_cur [NNODE];
__device__ int   g_bsrc[EDGES];
__device__ float g_bw  [EDGES];
__device__ float g_xg  [BB * DG];
__device__ float g_pert[BB * DG];
__device__ float g_h   [BB * DH];
__device__ float g_z   [BB * DH];
__device__ float g_t   [BB * DI];
__device__ float g_proj[BB * NCLS * RNK];

// bf16 hi/lo weight arrays, all in [N, K] layout (K contiguous)
__device__ __nv_bfloat16 g_gnnw_h[3 * DG * DG],        g_gnnw_l[3 * DG * DG];
__device__ __nv_bfloat16 g_postw_h[DG * DG],           g_postw_l[DG * DG];
__device__ __nv_bfloat16 g_pinw_h[DH * DG],            g_pinw_l[DH * DG];
__device__ __nv_bfloat16 g_w1_h[6 * DI * DH],          g_w1_l[6 * DI * DH];
__device__ __nv_bfloat16 g_w2_h[6 * DH * DI],          g_w2_l[6 * DH * DI];
__device__ __nv_bfloat16 g_pout_h[NCLS * RNK * DH],    g_pout_l[NCLS * RNK * DH];
__device__ __nv_bfloat16 g_gene_h[NGENE * RNK],        g_gene_l[NGENE * RNK];

// ---------------- small kernels ----------------
__global__ void zero_deg_kernel(int* deg) {
    int i = blockIdx.x * blockDim.x + threadIdx.x;
    if (i < NNODE) deg[i] = 0;
}
__global__ void hist_kernel(const int* __restrict__ ei, int* __restrict__ deg) {
    int i = blockIdx.x * blockDim.x + threadIdx.x;
    if (i < EDGES) atomicAdd(&deg[ei[EDGES + i]], 1);
}
__global__ void scan_kernel(const int* __restrict__ deg, int* __restrict__ off, int n) {
    __shared__ int sh[1024];
    __shared__ int base_s;
    int tid = threadIdx.x;
    if (tid == 0) { base_s = 0; off[0] = 0; }
    __syncthreads();
    for (int start = 0; start < n; start += 1024) {
        int v = (start + tid < n) ? deg[start + tid] : 0;
        sh[tid] = v;
        __syncthreads();
        for (int o = 1; o < 1024; o <<= 1) {
            int u = (tid >= o) ? sh[tid - o] : 0;
            __syncthreads();
            sh[tid] += u;
            __syncthreads();
        }
        if (start + tid < n) off[start + tid + 1] = base_s + sh[tid];
        int tot = sh[1023];
        __syncthreads();
        if (tid == 0) base_s += tot;
        __syncthreads();
    }
}
__global__ void copy_cursor_kernel(const int* __restrict__ off, int* __restrict__ cur) {
    int i = blockIdx.x * blockDim.x + threadIdx.x;
    if (i < NNODE) cur[i] = off[i];
}
__global__ void scatter_kernel(const int* __restrict__ ei, const float* __restrict__ ew,
                               int* __restrict__ cur, int* __restrict__ bsrc, float* __restrict__ bw) {
    int i = blockIdx.x * blockDim.x + threadIdx.x;
    if (i < EDGES) {
        int d = ei[EDGES + i];
        int p = atomicAdd(&cur[d], 1);
        bsrc[p] = ei[i];
        bw[p]   = ew[i];
    }
}
__global__ void copy_x_kernel(const float* __restrict__ src, float* __restrict__ dst) {
    int i = blockIdx.x * blockDim.x + threadIdx.x;
    if (i < NPAD * DG) dst[i] = (i < NNODE * DG) ? src[i] : 0.0f;
}
__global__ void ln_kernel(const float* __restrict__ x, const float* __restrict__ s,
                          const float* __restrict__ b, float* __restrict__ y,
                          int rows, int D) {
    int wid = threadIdx.x >> 5, lane = threadIdx.x & 31;
    int row = blockIdx.x * (blockDim.x >> 5) + wid;
    if (row >= rows) return;
    const float4* xr = (const float4*)(x + (size_t)row * D);
    int nf = D >> 7;
    float4 r[4];
    float sum = 0.f;
    for (int t = 0; t < nf; ++t) {
        r[t] = xr[lane + 32 * t];
        sum += r[t].x + r[t].y + r[t].z + r[t].w;
    }
    for (int o = 16; o > 0; o >>= 1) sum += __shfl_xor_sync(0xffffffffu, sum, o);
    float mu = sum / (float)D;
    float vs = 0.f;
    for (int t = 0; t < nf; ++t) {
        float dx = r[t].x - mu, dy = r[t].y - mu, dz = r[t].z - mu, dw = r[t].w - mu;
        vs += dx * dx + dy * dy + dz * dz + dw * dw;
    }
    for (int o = 16; o > 0; o >>= 1) vs += __shfl_xor_sync(0xffffffffu, vs, o);
    float w = rsqrtf(vs / (float)D + LN_EPS);
    float4* yr = (float4*)(y + (size_t)row * D);
    for (int t = 0; t < nf; ++t) {
        int col = (lane + 32 * t) * 4;
        float4 o4;
        o4.x = (r[t].x - mu) * w * s[col + 0] + b[col + 0];
        o4.y = (r[t].y - mu) * w * s[col + 1] + b[col + 1];
        o4.z = (r[t].z - mu) * w * s[col + 2] + b[col + 2];
        o4.w = (r[t].w - mu) * w * s[col + 3] + b[col + 3];
        yr[lane + 32 * t] = o4;
    }
}
__global__ void agg_kernel(const float* __restrict__ hln, float* __restrict__ agg,
                           const int* __restrict__ off, const int* __restrict__ bsrc,
                           const float* __restrict__ bw) {
    int wid = threadIdx.x >> 5, lane = threadIdx.x & 31;
    int node = blockIdx.x * (blockDim.x >> 5) + wid;
    if (node >= NNODE) return;
    int st = off[node], en = off[node + 1];
    float4 a0 = make_float4(0, 0, 0, 0), a1 = make_float4(0, 0, 0, 0);
    for (int j = st; j < en; ++j) {
        int s = bsrc[j];
        float w = bw[j];
        const float4* r = (const float4*)(hln + s * DG);
        float4 v0 = r[lane], v1 = r[lane + 32];
        a0.x = fmaf(w, v0.x, a0.x); a0.y = fmaf(w, v0.y, a0.y);
        a0.z = fmaf(w, v0.z, a0.z); a0.w = fmaf(w, v0.w, a0.w);
        a1.x = fmaf(w, v1.x, a1.x); a1.y = fmaf(w, v1.y, a1.y);
        a1.z = fmaf(w, v1.z, a1.z); a1.w = fmaf(w, v1.w, a1.w);
    }
    float4* o = (float4*)(agg + node * DG);
    o[lane] = a0;
    o[lane + 32] = a1;
}
__global__ void gather_kernel(const float* __restrict__ x, const int* __restrict__ idx,
                              float* __restrict__ out) {
    int bi = blockIdx.x, j = threadIdx.x;
    int id = idx[bi];
    int safe = id < 0 ? 0 : id;
    out[bi * DG + j] = x[(size_t)safe * DG + j];
}
__global__ void oovfix_kernel(const int* __restrict__ idx, const float* __restrict__ oov_emb,
                              float* __restrict__ pert) {
    int bi = blockIdx.x, j = threadIdx.x;
    if (idx[bi] < 0) pert[bi * DG + j] = oov_emb[j];
}

// ---------------- weight conversion kernels ----------------
// transpose + hi/lo bf16 split: in [K,N] fp32 (z-batched) -> out [N,K] bf16 pairs
__global__ void conv_t_kernel(const float* __restrict__ in, __nv_bfloat16* __restrict__ oh,
                              __nv_bfloat16* __restrict__ ol, int K, int N) {
    __shared__ float tbuf[32][33];
    size_t zoff = (size_t)blockIdx.z * K * N;
    const float* inz = in + zoff;
    __nv_bfloat16* ohz = oh + zoff;
    __nv_bfloat16* olz = ol + zoff;
    int n0 = blockIdx.x * 32, k0 = blockIdx.y * 32;
    int tx = threadIdx.x, ty = threadIdx.y;  // 32 x 8
    for (int dy = 0; dy < 32; dy += 8)
        tbuf[ty + dy][tx] = inz[(size_t)(k0 + ty + dy) * N + n0 + tx];
    __syncthreads();
    for (int dy = 0; dy < 32; dy += 8) {
        float v = tbuf[tx][ty + dy];
        __nv_bfloat16 h = __float2bfloat16(v);
        __nv_bfloat16 l = __float2bfloat16(v - __bfloat162float(h));
        size_t o = (size_t)(n0 + ty + dy) * K + k0 + tx;
        ohz[o] = h;
        olz[o] = l;
    }
}
// straight split (already [N,K])
__global__ void conv_n_kernel(const float* __restrict__ in, __nv_bfloat16* __restrict__ oh,
                              __nv_bfloat16* __restrict__ ol, int total) {
    int i = blockIdx.x * blockDim.x + threadIdx.x;
    if (i >= total) return;
    float v = in[i];
    __nv_bfloat16 h = __float2bfloat16(v);
    oh[i] = h;
    ol[i] = __float2bfloat16(v - __bfloat162float(h));
}

// ---------------- mma.sync bf16x3 GEMM ----------------
// C[M,N] = A[M,K](fp32) @ B[N,K]^T (bf16 hi/lo pre-split)
// Block tile 128x64, BK=32, 128 threads (4 warps, 2x2), warp tile 64x32.
enum { EPI_NONE = 0, EPI_BIAS = 1, EPI_RELU_RES = 2, EPI_ADD = 3, EPI_GELU = 4 };

#define SP 40   // smem row stride in bf16 elems (80B, conflict-free ldmatrix)

__device__ __forceinline__ uint32_t smem_u32(const void* p) {
    uint32_t a;
    asm("{ .reg .u64 t; cvta.to.shared.u64 t, %1; cvt.u32.u64 %0, t; }" : "=r"(a) : "l"(p));
    return a;
}
__device__ __forceinline__ void ldsm4(uint32_t* r, uint32_t addr) {
    asm volatile("ldmatrix.sync.aligned.m8n8.x4.shared.b16 {%0,%1,%2,%3}, [%4];"
                 : "=r"(r[0]), "=r"(r[1]), "=r"(r[2]), "=r"(r[3]) : "r"(addr));
}
__device__ __forceinline__ void ldsm2(uint32_t* r, uint32_t addr) {
    asm volatile("ldmatrix.sync.aligned.m8n8.x2.shared.b16 {%0,%1}, [%2];"
                 : "=r"(r[0]), "=r"(r[1]) : "r"(addr));
}
__device__ __forceinline__ void mma16816(float* d, const uint32_t* a, const uint32_t* b) {
    asm volatile("mma.sync.aligned.m16n8k16.row.col.f32.bf16.bf16.f32 "
                 "{%0,%1,%2,%3}, {%4,%5,%6,%7}, {%8,%9}, {%0,%1,%2,%3};"
                 : "+f"(d[0]), "+f"(d[1]), "+f"(d[2]), "+f"(d[3])
                 : "r"(a[0]), "r"(a[1]), "r"(a[2]), "r"(a[3]), "r"(b[0]), "r"(b[1]));
}

template <int EPI>
__global__ void __launch_bounds__(128) gemm_mma_kernel(
    const float* __restrict__ A, const __nv_bfloat16* __restrict__ Bh,
    const __nv_bfloat16* __restrict__ Bl, const float* __restrict__ bias,
    const float* __restrict__ res, float* __restrict__ C, int M, int N, int K)
{
    __shared__ __nv_bfloat16 Ah[128 * SP], Al[128 * SP], Bhs[64 * SP], Bls[64 * SP];

    int t = threadIdx.x, wid = t >> 5, lane = t & 31;
    int m0 = blockIdx.y * 128, n0 = blockIdx.x * 64;
    int wm = (wid >> 1) * 64, wn = (wid & 1) * 32;

    float acc[4][4][4];
#pragma unroll
    for (int i = 0; i < 4; ++i)
#pragma unroll
        for (int j = 0; j < 4; ++j)
#pragma unroll
            for (int c = 0; c < 4; ++c) acc[i][j][c] = 0.f;

    uint32_t sAh = smem_u32(Ah), sAl = smem_u32(Al);
    uint32_t sBh = smem_u32(Bhs), sBl = smem_u32(Bls);

    int nkb = K >> 5;
    for (int kb = 0; kb < nkb; ++kb) {
        // ---- A tile: 128 x 32 fp32 -> bf16 hi/lo ----
        {
            int col4 = t & 7;               // float4 index (k offset col4*4)
            int rbase = t >> 3;             // 0..15
#pragma unroll
            for (int it = 0; it < 8; ++it) {
                int row = it * 16 + rbase;
                const float4 v = *(const float4*)(A + (size_t)(m0 + row) * K + (kb << 5) + col4 * 4);
                __nv_bfloat16 h0 = __float2bfloat16(v.x), h1 = __float2bfloat16(v.y);
                __nv_bfloat16 h2 = __float2bfloat16(v.z), h3 = __float2bfloat16(v.w);
                __nv_bfloat16 l0 = __float2bfloat16(v.x - __bfloat162float(h0));
                __nv_bfloat16 l1 = __float2bfloat16(v.y - __bfloat162float(h1));
                __nv_bfloat16 l2 = __float2bfloat16(v.z - __bfloat162float(h2));
                __nv_bfloat16 l3 = __float2bfloat16(v.w - __bfloat162float(h3));
                uint2 hp, lp;
                hp.x = (uint32_t)__bfloat16_as_ushort(h0) | ((uint32_t)__bfloat16_as_ushort(h1) << 16);
                hp.y = (uint32_t)__bfloat16_as_ushort(h2) | ((uint32_t)__bfloat16_as_ushort(h3) << 16);
                lp.x = (uint32_t)__bfloat16_as_ushort(l0) | ((uint32_t)__bfloat16_as_ushort(l1) << 16);
                lp.y = (uint32_t)__bfloat16_as_ushort(l2) | ((uint32_t)__bfloat16_as_ushort(l3) << 16);
                *(uint2*)(Ah + row * SP + col4 * 4) = hp;
                *(uint2*)(Al + row * SP + col4 * 4) = lp;
            }
        }
        // ---- B tile: 64 x 32 bf16 hi/lo (pre-split, [N,K]); zero-fill OOB ----
        {
            int kc = (t & 3) * 8;           // bf16 elem offset (16B chunks)
            int nbase = t >> 2;             // 0..31
#pragma unroll
            for (int it = 0; it < 2; ++it) {
                int nl = it * 32 + nbase;
                int gn = n0 + nl;
                uint4 vh = make_uint4(0, 0, 0, 0), vl = make_uint4(0, 0, 0, 0);
                if (gn < N) {
                    vh = *(const uint4*)(Bh + (size_t)gn * K + (kb << 5) + kc);
                    vl = *(const uint4*)(Bl + (size_t)gn * K + (kb << 5) + kc);
                }
                *(uint4*)(Bhs + nl * SP + kc) = vh;
                *(uint4*)(Bls + nl * SP + kc) = vl;
            }
        }
        __syncthreads();
        // ---- 2 k16 steps ----
#pragma unroll
        for (int ks = 0; ks < 2; ++ks) {
            uint32_t aH[4][4], aL[4][4], bH[4][2], bL[4][2];
            uint32_t aoff = (uint32_t)((ks * 16 + (lane >> 4) * 8) * 2);   // byte col offset
            uint32_t boff = (uint32_t)((ks * 16 + ((lane >> 3) & 1) * 8) * 2);
#pragma unroll
            for (int mt = 0; mt < 4; ++mt) {
                uint32_t rowb = (uint32_t)((wm + mt * 16 + (lane & 15)) * SP * 2);
                ldsm4(aH[mt], sAh + rowb + aoff);
                ldsm4(aL[mt], sAl + rowb + aoff);
            }
#pragma unroll
            for (int nt = 0; nt < 4; ++nt) {
                uint32_t rowb = (uint32_t)((wn + nt * 8 + (lane & 7)) * SP * 2);
                ldsm2(bH[nt], sBh + rowb + boff);
                ldsm2(bL[nt], sBl + rowb + boff);
            }
#pragma unroll
            for (int mt = 0; mt < 4; ++mt)
#pragma unroll
                for (int nt = 0; nt < 4; ++nt) {
                    mma16816(acc[mt][nt], aH[mt], bH[nt]);
                    mma16816(acc[mt][nt], aH[mt], bL[nt]);
                    mma16816(acc[mt][nt], aL[mt], bH[nt]);
                }
        }
        __syncthreads();
    }

    // ---- epilogue ----
    int grp = lane >> 2, tig = lane & 3;
#pragma unroll
    for (int mt = 0; mt < 4; ++mt) {
#pragma unroll
        for (int nt = 0; nt < 4; ++nt) {
            int gn = n0 + wn + nt * 8 + tig * 2;
#pragma unroll
            for (int hh = 0; hh < 2; ++hh) {
                int gm = m0 + wm + mt * 16 + grp + hh * 8;
                float v0 = acc[mt][nt][hh * 2 + 0];
                float v1 = acc[mt][nt][hh * 2 + 1];
                if (EPI == EPI_BIAS) {
                    v0 += bias[gn]; v1 += bias[gn + 1];
                } else if (EPI == EPI_RELU_RES) {
                    v0 = fmaxf(v0 + bias[gn], 0.f)     + res[(size_t)gm * N + gn];
                    v1 = fmaxf(v1 + bias[gn + 1], 0.f) + res[(size_t)gm * N + gn + 1];
                } else if (EPI == EPI_ADD) {
                    v0 += bias[gn]     + res[(size_t)gm * N + gn];
                    v1 += bias[gn + 1] + res[(size_t)gm * N + gn + 1];
                } else if (EPI == EPI_GELU) {
                    v0 += bias[gn]; v1 += bias[gn + 1];
                    v0 = 0.5f * v0 * (1.f + erff(v0 * 0.70710678118654752f));
                    v1 = 0.5f * v1 * (1.f + erff(v1 * 0.70710678118654752f));
                }
                if (gn + 1 < N) {
                    *(float2*)(C + (size_t)gm * N + gn) = make_float2(v0, v1);
                } else if (gn < N) {
                    C[(size_t)gm * N + gn] = v0;
                }
            }
        }
    }
}

// ---------------- launch ----------------
extern "C" void kernel_launch(void* const* d_in, const int* in_sizes, int n_in,
                              void* d_out, int out_size) {
    const int*   node_indices = (const int*)d_in[0];
    const int*   edge_index   = (const int*)d_in[1];
    const float* edge_weight  = (const float*)d_in[2];
    const float* partial_emb  = (const float*)d_in[3];
    const float* oov_emb      = (const float*)d_in[4];
    const float* gnn_ln_s     = (const float*)d_in[5];
    const float* gnn_ln_b     = (const float*)d_in[6];
    const float* gnn_w        = (const float*)d_in[7];
    const float* gnn_b        = (const float*)d_in[8];
    const float* post_w       = (const float*)d_in[9];
    const float* post_b       = (const float*)d_in[10];
    const float* pin_w        = (const float*)d_in[11];
    const float* pin_b        = (const float*)d_in[12];
    const float* blk_ln_s     = (const float*)d_in[13];
    const float* blk_ln_b     = (const float*)d_in[14];
    const float* blk_w1       = (const float*)d_in[15];
    const float* blk_b1       = (const float*)d_in[16];
    const float* blk_w2       = (const float*)d_in[17];
    const float* blk_b2       = (const float*)d_in[18];
    const float* pout_w       = (const float*)d_in[19];
    const float* pout_b       = (const float*)d_in[20];
    const float* gene         = (const float*)d_in[21];
    float*       out          = (float*)d_out;

    static float *p_x = nullptr, *p_hln, *p_agg, *p_bw, *p_xg, *p_pert, *p_h, *p_z, *p_t, *p_proj;
    static int   *p_deg, *p_off, *p_cur, *p_bsrc;
    static __nv_bfloat16 *w_gnn_h, *w_gnn_l, *w_post_h, *w_post_l, *w_pin_h, *w_pin_l,
                         *w_w1_h, *w_w1_l, *w_w2_h, *w_w2_l, *w_pout_h, *w_pout_l,
                         *w_gene_h, *w_gene_l;
    if (!p_x) {
        cudaGetSymbolAddress((void**)&p_x,    g_x);
        cudaGetSymbolAddress((void**)&p_hln,  g_hln);
        cudaGetSymbolAddress((void**)&p_agg,  g_agg);
        cudaGetSymbolAddress((void**)&p_bw,   g_bw);
        cudaGetSymbolAddress((void**)&p_xg,   g_xg);
        cudaGetSymbolAddress((void**)&p_pert, g_pert);
        cudaGetSymbolAddress((void**)&p_h,    g_h);
        cudaGetSymbolAddress((void**)&p_z,    g_z);
        cudaGetSymbolAddress((void**)&p_t,    g_t);
        cudaGetSymbolAddress((void**)&p_proj, g_proj);
        cudaGetSymbolAddress((void**)&p_deg,  g_deg);
        cudaGetSymbolAddress((void**)&p_off,  g_off);
        cudaGetSymbolAddress((void**)&p_cur,  g_cur);
        cudaGetSymbolAddress((void**)&p_bsrc, g_bsrc);
        cudaGetSymbolAddress((void**)&w_gnn_h,  g_gnnw_h);
        cudaGetSymbolAddress((void**)&w_gnn_l,  g_gnnw_l);
        cudaGetSymbolAddress((void**)&w_post_h, g_postw_h);
        cudaGetSymbolAddress((void**)&w_post_l, g_postw_l);
        cudaGetSymbolAddress((void**)&w_pin_h,  g_pinw_h);
        cudaGetSymbolAddress((void**)&w_pin_l,  g_pinw_l);
        cudaGetSymbolAddress((void**)&w_w1_h,   g_w1_h);
        cudaGetSymbolAddress((void**)&w_w1_l,   g_w1_l);
        cudaGetSymbolAddress((void**)&w_w2_h,   g_w2_h);
        cudaGetSymbolAddress((void**)&w_w2_l,   g_w2_l);
        cudaGetSymbolAddress((void**)&w_pout_h, g_pout_h);
        cudaGetSymbolAddress((void**)&w_pout_l, g_pout_l);
        cudaGetSymbolAddress((void**)&w_gene_h, g_gene_h);
        cudaGetSymbolAddress((void**)&w_gene_l, g_gene_l);
    }

    dim3 tb32(32, 8);
    // ---- weight conversions (transpose [K,N]->[N,K] + bf16 hi/lo split) ----
    conv_t_kernel<<<dim3(DG / 32, DG / 32, 3), tb32>>>(gnn_w,  w_gnn_h,  w_gnn_l,  DG, DG);
    conv_t_kernel<<<dim3(DG / 32, DG / 32, 1), tb32>>>(post_w, w_post_h, w_post_l, DG, DG);
    conv_t_kernel<<<dim3(DH / 32, DG / 32, 1), tb32>>>(pin_w,  w_pin_h,  w_pin_l,  DG, DH);
    conv_t_kernel<<<dim3(DI / 32, DH / 32, 6), tb32>>>(blk_w1, w_w1_h,   w_w1_l,   DH, DI);
    conv_t_kernel<<<dim3(DH / 32, DI / 32, 6), tb32>>>(blk_w2, w_w2_h,   w_w2_l,   DI, DH);
    conv_t_kernel<<<dim3((NCLS * RNK) / 32, DH / 32, 1), tb32>>>(pout_w, w_pout_h, w_pout_l, DH, NCLS * RNK);
    conv_n_kernel<<<(NGENE * RNK + 255) / 256, 256>>>(gene, w_gene_h, w_gene_l, NGENE * RNK);

    // ---- CSR binning of edges by dst ----
    zero_deg_kernel<<<(NNODE + 255) / 256, 256>>>(p_deg);
    hist_kernel<<<(EDGES + 255) / 256, 256>>>(edge_index, p_deg);
    scan_kernel<<<1, 1024>>>(p_deg, p_off, NNODE);
    copy_cursor_kernel<<<(NNODE + 255) / 256, 256>>>(p_off, p_cur);
    scatter_kernel<<<(EDGES + 255) / 256, 256>>>(edge_index, edge_weight, p_cur, p_bsrc, p_bw);

    // ---- x = partial_emb (pad rows zero) ----
    copy_x_kernel<<<(NPAD * DG + 255) / 256, 256>>>(partial_emb, p_x);

    // ---- 3 GNN layers ----
    for (int i = 0; i < 3; ++i) {
        ln_kernel<<<NPAD / 8, 256>>>(p_x, gnn_ln_s + i * DG, gnn_ln_b + i * DG, p_hln, NPAD, DG);
        agg_kernel<<<(NNODE + 7) / 8, 256>>>(p_hln, p_agg, p_off, p_bsrc, p_bw);
        gemm_mma_kernel<EPI_RELU_RES><<<dim3(DG / 64, NPAD / 128), 128>>>(
            p_agg, w_gnn_h + (size_t)i * DG * DG, w_gnn_l + (size_t)i * DG * DG,
            gnn_b + i * DG, p_x, p_x, NPAD, DG, DG);
    }

    // ---- gather 256 rows, post_mp on just those rows ----
    gather_kernel<<<BB, DG>>>(p_x, node_indices, p_xg);
    gemm_mma_kernel<EPI_BIAS><<<dim3(DG / 64, BB / 128), 128>>>(
        p_xg, w_post_h, w_post_l, post_b, nullptr, p_pert, BB, DG, DG);
    oovfix_kernel<<<BB, DG>>>(node_indices, oov_emb, p_pert);

    // ---- proj_in ----
    gemm_mma_kernel<EPI_BIAS><<<dim3(DH / 64, BB / 128), 128>>>(
        p_pert, w_pin_h, w_pin_l, pin_b, nullptr, p_h, BB, DH, DG);

    // ---- 6 residual MLP blocks ----
    for (int i = 0; i < 6; ++i) {
        ln_kernel<<<BB / 8, 256>>>(p_h, blk_ln_s + i * DH, blk_ln_b + i * DH, p_z, BB, DH);
        gemm_mma_kernel<EPI_GELU><<<dim3(DI / 64, BB / 128), 128>>>(
            p_z, w_w1_h + (size_t)i * DI * DH, w_w1_l + (size_t)i * DI * DH,
            blk_b1 + i * DI, nullptr, p_t, BB, DI, DH);
        gemm_mma_kernel<EPI_ADD><<<dim3(DH / 64, BB / 128), 128>>>(
            p_t, w_w2_h + (size_t)i * DH * DI, w_w2_l + (size_t)i * DH * DI,
            blk_b2 + i * DH, p_h, p_h, BB, DH, DI);
    }

    // ---- proj_out ----
    gemm_mma_kernel<EPI_BIAS><<<dim3((NCLS * RNK) / 64, BB / 128), 128>>>(
        p_h, w_pout_h, w_pout_l, pout_b, nullptr, p_proj, BB, NCLS * RNK, DH);

    // ---- logits = proj[768,512] @ gene[6640,512]^T ----
    gemm_mma_kernel<EPI_NONE><<<dim3((NGENE + 63) / 64, (BB * NCLS) / 128), 128>>>(
        p_proj, w_gene_h, w_gene_l, nullptr, nullptr, out, BB * NCLS, NGENE, RNK);
}

// round 5
// speedup vs baseline: 1.0825x; 1.0825x over previous
#include <cuda_runtime.h>
#include <math.h>

// ---------------- problem constants ----------------
#define NNODE   20000
#define NPAD    20096          // padded to multiple of 128 for GEMM
#define EDGES   640000
#define BB      256            // batch
#define DG      256            // GNN dim
#define DH      512            // hidden
#define DI      2048           // inner
#define RNK     512
#define NCLS    3
#define NGENE   6640
#define LN_EPS  1e-5f

// ---------------- scratch (device globals; no allocation allowed) ----------------
__device__ float g_x   [NPAD * DG];
__device__ float g_hln [NPAD * DG];
__device__ float g_agg [NPAD * DG];   // pad rows never written -> stay zero
__device__ int   g_deg [NNODE];
__device__ int   g_off [NNODE + 1];
__device__ int   g_cur [NNODE];
__device__ int   g_bsrc[EDGES];
__device__ float g_bw  [EDGES];
__device__ float g_xg  [BB * DG];
__device__ float g_pert[BB * DG];
__device__ float g_h   [BB * DH];
__device__ float g_z   [BB * DH];
__device__ float g_t   [BB * DI];
__device__ float g_part[8 * BB * DI];     // split-K partials
__device__ float g_proj[BB * NCLS * RNK];
// frontier state
__device__ int   g_flag2[NNODE];
__device__ int   g_flag3[NNODE];
__device__ int   g_list2[NNODE];
__device__ int   g_list3[BB];
__device__ int   g_cnt2[1];

// ---------------- packed f32x2 helpers ----------------
__device__ __forceinline__ void ffma2(unsigned long long &d, unsigned long long a, unsigned long long b) {
    asm("fma.rn.f32x2 %0, %1, %2, %0;" : "+l"(d) : "l"(a), "l"(b));
}
__device__ __forceinline__ unsigned long long pack2(float x, float y) {
    unsigned long long r;
    asm("mov.b64 %0, {%1, %2};" : "=l"(r) : "f"(x), "f"(y));
    return r;
}
__device__ __forceinline__ float lo2(unsigned long long v) {
    return __uint_as_float((unsigned)(v & 0xffffffffull));
}
__device__ __forceinline__ float hi2(unsigned long long v) {
    return __uint_as_float((unsigned)(v >> 32));
}

// ---------------- small kernels ----------------
__global__ void zero_deg_kernel(int* deg) {
    int i = blockIdx.x * blockDim.x + threadIdx.x;
    if (i < NNODE) deg[i] = 0;
}

__global__ void hist_kernel(const int* __restrict__ ei, int* __restrict__ deg) {
    int i = blockIdx.x * blockDim.x + threadIdx.x;
    if (i < EDGES) atomicAdd(&deg[ei[EDGES + i]], 1);
}

__global__ void scan_kernel(const int* __restrict__ deg, int* __restrict__ off, int n) {
    __shared__ int sh[1024];
    __shared__ int base_s;
    int tid = threadIdx.x;
    if (tid == 0) { base_s = 0; off[0] = 0; }
    __syncthreads();
    for (int start = 0; start < n; start += 1024) {
        int v = (start + tid < n) ? deg[start + tid] : 0;
        sh[tid] = v;
        __syncthreads();
        for (int o = 1; o < 1024; o <<= 1) {
            int u = (tid >= o) ? sh[tid - o] : 0;
            __syncthreads();
            sh[tid] += u;
            __syncthreads();
        }
        if (start + tid < n) off[start + tid + 1] = base_s + sh[tid];
        int tot = sh[1023];
        __syncthreads();
        if (tid == 0) base_s += tot;
        __syncthreads();
    }
}

__global__ void copy_cursor_kernel(const int* __restrict__ off, int* __restrict__ cur) {
    int i = blockIdx.x * blockDim.x + threadIdx.x;
    if (i < NNODE) cur[i] = off[i];
}

__global__ void scatter_kernel(const int* __restrict__ ei, const float* __restrict__ ew,
                               int* __restrict__ cur, int* __restrict__ bsrc, float* __restrict__ bw) {
    int i = blockIdx.x * blockDim.x + threadIdx.x;
    if (i < EDGES) {
        int d = ei[EDGES + i];
        int p = atomicAdd(&cur[d], 1);
        bsrc[p] = ei[i];
        bw[p]   = ew[i];
    }
}

__global__ void copy_x_kernel(const float* __restrict__ src, float* __restrict__ dst) {
    int i = blockIdx.x * blockDim.x + threadIdx.x;
    if (i < NPAD * DG) dst[i] = (i < NNODE * DG) ? src[i] : 0.0f;
}

// ---- frontier kernels ----
__global__ void flag_init_kernel(int* flag2, int* flag3, int* cnt2) {
    int i = blockIdx.x * blockDim.x + threadIdx.x;
    if (i < NNODE) { flag2[i] = 0; flag3[i] = 0; }
    if (i == 0) cnt2[0] = 0;
}
__global__ void flag_seed_kernel(const int* __restrict__ idx, int* flag2, int* flag3, int* list3) {
    int i = threadIdx.x;  // BB threads
    int id = idx[i];
    int safe = id < 0 ? 0 : id;
    flag3[safe] = 1;
    flag2[safe] = 1;
    list3[i] = safe;
}
__global__ void flag_edge_kernel(const int* __restrict__ ei, const int* __restrict__ flag3,
                                 int* __restrict__ flag2) {
    int e = blockIdx.x * blockDim.x + threadIdx.x;
    if (e < EDGES && flag3[ei[EDGES + e]]) flag2[ei[e]] = 1;
}
__global__ void compact_kernel(const int* __restrict__ flag2, int* __restrict__ list2,
                               int* __restrict__ cnt2) {
    int i = blockIdx.x * blockDim.x + threadIdx.x;
    if (i < NNODE && flag2[i]) {
        int p = atomicAdd(cnt2, 1);
        list2[p] = i;
    }
}

// LayerNorm: one warp per row. D in {256, 512}.
__global__ void ln_kernel(const float* __restrict__ x, const float* __restrict__ s,
                          const float* __restrict__ b, float* __restrict__ y,
                          int rows, int D) {
    int wid = threadIdx.x >> 5, lane = threadIdx.x & 31;
    int row = blockIdx.x * (blockDim.x >> 5) + wid;
    if (row >= rows) return;
    const float4* xr = (const float4*)(x + (size_t)row * D);
    int nf = D >> 7;
    float4 r[4];
    float sum = 0.f;
    for (int t = 0; t < nf; ++t) {
        r[t] = xr[lane + 32 * t];
        sum += r[t].x + r[t].y + r[t].z + r[t].w;
    }
    for (int o = 16; o > 0; o >>= 1) sum += __shfl_xor_sync(0xffffffffu, sum, o);
    float mu = sum / (float)D;
    float vs = 0.f;
    for (int t = 0; t < nf; ++t) {
        float dx = r[t].x - mu, dy = r[t].y - mu, dz = r[t].z - mu, dw = r[t].w - mu;
        vs += dx * dx + dy * dy + dz * dz + dw * dw;
    }
    for (int o = 16; o > 0; o >>= 1) vs += __shfl_xor_sync(0xffffffffu, vs, o);
    float w = rsqrtf(vs / (float)D + LN_EPS);
    float4* yr = (float4*)(y + (size_t)row * D);
    for (int t = 0; t < nf; ++t) {
        int col = (lane + 32 * t) * 4;
        float4 o4;
        o4.x = (r[t].x - mu) * w * s[col + 0] + b[col + 0];
        o4.y = (r[t].y - mu) * w * s[col + 1] + b[col + 1];
        o4.z = (r[t].z - mu) * w * s[col + 2] + b[col + 2];
        o4.w = (r[t].w - mu) * w * s[col + 3] + b[col + 3];
        yr[lane + 32 * t] = o4;
    }
}

// CSR weighted aggregation: one warp per node; optional frontier flag skip.
__global__ void agg_kernel(const float* __restrict__ hln, float* __restrict__ agg,
                           const int* __restrict__ off, const int* __restrict__ bsrc,
                           const float* __restrict__ bw, const int* __restrict__ flag) {
    int wid = threadIdx.x >> 5, lane = threadIdx.x & 31;
    int node = blockIdx.x * (blockDim.x >> 5) + wid;
    if (node >= NNODE) return;
    if (flag && !flag[node]) return;
    int st = off[node], en = off[node + 1];
    float4 a0 = make_float4(0, 0, 0, 0), a1 = make_float4(0, 0, 0, 0);
    for (int j = st; j < en; ++j) {
        int s = bsrc[j];
        float w = bw[j];
        const float4* r = (const float4*)(hln + s * DG);
        float4 v0 = r[lane], v1 = r[lane + 32];
        a0.x = fmaf(w, v0.x, a0.x); a0.y = fmaf(w, v0.y, a0.y);
        a0.z = fmaf(w, v0.z, a0.z); a0.w = fmaf(w, v0.w, a0.w);
        a1.x = fmaf(w, v1.x, a1.x); a1.y = fmaf(w, v1.y, a1.y);
        a1.z = fmaf(w, v1.z, a1.z); a1.w = fmaf(w, v1.w, a1.w);
    }
    float4* o = (float4*)(agg + node * DG);
    o[lane] = a0;
    o[lane + 32] = a1;
}

__global__ void gather_kernel(const float* __restrict__ x, const int* __restrict__ idx,
                              float* __restrict__ out) {
    int bi = blockIdx.x, j = threadIdx.x;
    int id = idx[bi];
    int safe = id < 0 ? 0 : id;
    out[bi * DG + j] = x[(size_t)safe * DG + j];
}

__global__ void oovfix_kernel(const int* __restrict__ idx, const float* __restrict__ oov_emb,
                              float* __restrict__ pert) {
    int bi = blockIdx.x, j = threadIdx.x;
    if (idx[bi] < 0) pert[bi * DG + j] = oov_emb[j];
}

// Split-K reduce with epilogue.
// mode 0: dst = bias + sum ; mode 1: dst += bias + sum ; mode 2: dst = gelu(bias + sum)
__global__ void reduce_kernel(float* __restrict__ dst, const float* __restrict__ part,
                              const float* __restrict__ bias, int S, int total, int N, int mode) {
    int i = blockIdx.x * blockDim.x + threadIdx.x;
    if (i >= total) return;
    float v = bias[i % N];
    for (int z = 0; z < S; ++z) v += part[(size_t)z * total + i];
    if (mode == 2) v = 0.5f * v * (1.f + erff(v * 0.70710678118654752f));
    if (mode == 1) dst[i] += v;
    else           dst[i] = v;
}

// ---------------- GEMM: 128x64 tile, BK=16, 128 threads, 8x8 microtile (f32x2) ----
// Double-buffered SMEM; optional row gather/scatter list + device row count.
enum { EPI_NONE = 0, EPI_BIAS = 1, EPI_RELU_RES = 2 };

template <bool BT>   // BT=false: B row-major [K,N];  BT=true: B row-major [N,K] (C = A @ B^T)
__global__ void __launch_bounds__(128) gemmx_kernel(
    const float* __restrict__ A, const float* __restrict__ B,
    const float* __restrict__ bias, const float* __restrict__ res,
    float* __restrict__ C, const int* __restrict__ rows, const int* __restrict__ cntp,
    int M, int N, int K, int kChunk, int epi)
{
    __shared__ float As[2][16][132];   // [stage][k][m]
    __shared__ float Bs[2][16][68];    // [stage][k][n]
    int Meff = cntp ? *cntp : M;
    int t  = threadIdx.x;
    int m0 = blockIdx.y * 128;
    if (m0 >= Meff) return;
    int n0 = blockIdx.x * 64;
    int ks = blockIdx.z * kChunk;
    int ke = ks + kChunk; if (ke > K) ke = K;
    int nkb = (ke - ks) >> 4;

    int tx8 = (t & 7) * 8;
    int ty8 = (t >> 3) * 8;

    // A load geometry: per j in 0..3: row = 32j + (t>>2), kc = (t&3)*4
    int rA = t >> 2, kcA = (t & 3) << 2;
    const float* Aptr[4];
    int rowA[4];
#pragma unroll
    for (int j = 0; j < 4; ++j) {
        int lm = m0 + 32 * j + rA;
        rowA[j] = 32 * j + rA;
        int grow = 0;
        bool ok = lm < Meff;
        if (ok) grow = rows ? rows[lm] : lm;
        Aptr[j] = ok ? (A + (size_t)grow * K + kcA) : nullptr;
    }
    // B load geometry
    int krB0 = 0, ncB = 0, rB = 0, kcB = 0;
    const float* Bptr[2] = {nullptr, nullptr};
    if (!BT) {
        krB0 = t >> 4;             // + 8j
        ncB  = (t & 15) << 2;
        int gn = n0 + ncB;
        if (gn < N) Bptr[0] = B + (size_t)krB0 * N + gn;   // advance by k later
    } else {
        rB  = t >> 2;              // n-row: 32j + rB
        kcB = (t & 3) << 2;
#pragma unroll
        for (int j = 0; j < 2; ++j) {
            int gn = n0 + 32 * j + rB;
            if (gn < N) Bptr[j] = B + (size_t)gn * K + kcB;
        }
    }

    unsigned long long acc[4][8];
#pragma unroll
    for (int p = 0; p < 4; ++p)
#pragma unroll
        for (int j = 0; j < 8; ++j) acc[p][j] = 0ull;

    float4 va[4], vb[2];

    // fetch helpers (into registers)
    auto fetch = [&](int k0) {
#pragma unroll
        for (int j = 0; j < 4; ++j)
            va[j] = Aptr[j] ? *(const float4*)(Aptr[j] + k0) : make_float4(0, 0, 0, 0);
        if (!BT) {
#pragma unroll
            for (int j = 0; j < 2; ++j)
                vb[j] = Bptr[0] ? *(const float4*)(Bptr[0] + (size_t)(k0 + 8 * j) * N)
                                : make_float4(0, 0, 0, 0);
        } else {
#pragma unroll
            for (int j = 0; j < 2; ++j)
                vb[j] = Bptr[j] ? *(const float4*)(Bptr[j] + k0) : make_float4(0, 0, 0, 0);
        }
    };
    auto store = [&](int st) {
#pragma unroll
        for (int j = 0; j < 4; ++j) {
            As[st][kcA + 0][rowA[j]] = va[j].x;
            As[st][kcA + 1][rowA[j]] = va[j].y;
            As[st][kcA + 2][rowA[j]] = va[j].z;
            As[st][kcA + 3][rowA[j]] = va[j].w;
        }
        if (!BT) {
#pragma unroll
            for (int j = 0; j < 2; ++j)
                *(float4*)&Bs[st][krB0 + 8 * j][ncB] = vb[j];
        } else {
#pragma unroll
            for (int j = 0; j < 2; ++j) {
                Bs[st][kcB + 0][32 * j + rB] = vb[j].x;
                Bs[st][kcB + 1][32 * j + rB] = vb[j].y;
                Bs[st][kcB + 2][32 * j + rB] = vb[j].z;
                Bs[st][kcB + 3][32 * j + rB] = vb[j].w;
            }
        }
    };

    // prologue
    fetch(ks);
    store(0);
    __syncthreads();

    for (int i = 0; i < nkb; ++i) {
        int cur = i & 1;
        bool have = (i + 1) < nkb;
        if (have) fetch(ks + ((i + 1) << 4));
#pragma unroll
        for (int kk = 0; kk < 16; ++kk) {
            const float* Ar = &As[cur][kk][ty8];
            unsigned long long a0 = *(const unsigned long long*)(Ar + 0);
            unsigned long long a1 = *(const unsigned long long*)(Ar + 2);
            unsigned long long a2 = *(const unsigned long long*)(Ar + 4);
            unsigned long long a3 = *(const unsigned long long*)(Ar + 6);
            float4 b0 = *(const float4*)&Bs[cur][kk][tx8];
            float4 b1 = *(const float4*)&Bs[cur][kk][tx8 + 4];
            unsigned long long bd[8];
            bd[0] = pack2(b0.x, b0.x); bd[1] = pack2(b0.y, b0.y);
            bd[2] = pack2(b0.z, b0.z); bd[3] = pack2(b0.w, b0.w);
            bd[4] = pack2(b1.x, b1.x); bd[5] = pack2(b1.y, b1.y);
            bd[6] = pack2(b1.z, b1.z); bd[7] = pack2(b1.w, b1.w);
#pragma unroll
            for (int j = 0; j < 8; ++j) {
                ffma2(acc[0][j], a0, bd[j]);
                ffma2(acc[1][j], a1, bd[j]);
                ffma2(acc[2][j], a2, bd[j]);
                ffma2(acc[3][j], a3, bd[j]);
            }
        }
        if (have) store(cur ^ 1);
        __syncthreads();
    }

    float* Cz = C + (size_t)blockIdx.z * M * N;
    bool nfull = (n0 + 64 <= N);
#pragma unroll
    for (int p = 0; p < 4; ++p) {
#pragma unroll
        for (int h = 0; h < 2; ++h) {
            int gm = m0 + ty8 + 2 * p + h;
            if (gm >= Meff) continue;
            int rr = rows ? rows[gm] : gm;
            float v[8];
#pragma unroll
            for (int j = 0; j < 8; ++j) v[j] = h ? hi2(acc[p][j]) : lo2(acc[p][j]);
            int gn0 = n0 + tx8;
            if (epi == EPI_RELU_RES) {
#pragma unroll
                for (int j = 0; j < 8; ++j) {
                    float bi = bias[gn0 + j];
                    float rv = res[(size_t)rr * N + gn0 + j];
                    v[j] = fmaxf(v[j] + bi, 0.f) + rv;
                }
            } else if (epi == EPI_BIAS) {
#pragma unroll
                for (int j = 0; j < 8; ++j) v[j] += bias[gn0 + j];
            }
            float* crow = rows ? (C + (size_t)rr * N) : (Cz + (size_t)gm * N);
            if (nfull) {
                *(float4*)(crow + gn0)     = make_float4(v[0], v[1], v[2], v[3]);
                *(float4*)(crow + gn0 + 4) = make_float4(v[4], v[5], v[6], v[7]);
            } else {
#pragma unroll
                for (int j = 0; j < 8; ++j)
                    if (gn0 + j < N) crow[gn0 + j] = v[j];
            }
        }
    }
}

// ---------------- launch ----------------
extern "C" void kernel_launch(void* const* d_in, const int* in_sizes, int n_in,
                              void* d_out, int out_size) {
    const int*   node_indices = (const int*)d_in[0];
    const int*   edge_index   = (const int*)d_in[1];
    const float* edge_weight  = (const float*)d_in[2];
    const float* partial_emb  = (const float*)d_in[3];
    const float* oov_emb      = (const float*)d_in[4];
    const float* gnn_ln_s     = (const float*)d_in[5];
    const float* gnn_ln_b     = (const float*)d_in[6];
    const float* gnn_w        = (const float*)d_in[7];
    const float* gnn_b        = (const float*)d_in[8];
    const float* post_w       = (const float*)d_in[9];
    const float* post_b       = (const float*)d_in[10];
    const float* pin_w        = (const float*)d_in[11];
    const float* pin_b        = (const float*)d_in[12];
    const float* blk_ln_s     = (const float*)d_in[13];
    const float* blk_ln_b     = (const float*)d_in[14];
    const float* blk_w1       = (const float*)d_in[15];
    const float* blk_b1       = (const float*)d_in[16];
    const float* blk_w2       = (const float*)d_in[17];
    const float* blk_b2       = (const float*)d_in[18];
    const float* pout_w       = (const float*)d_in[19];
    const float* pout_b       = (const float*)d_in[20];
    const float* gene         = (const float*)d_in[21];
    float*       out          = (float*)d_out;

    static float *p_x = nullptr, *p_hln, *p_agg, *p_bw, *p_xg, *p_pert, *p_h, *p_z, *p_t, *p_part, *p_proj;
    static int   *p_deg, *p_off, *p_cur, *p_bsrc;
    static int   *p_flag2, *p_flag3, *p_list2, *p_list3, *p_cnt2;
    if (!p_x) {
        cudaGetSymbolAddress((void**)&p_x,    g_x);
        cudaGetSymbolAddress((void**)&p_hln,  g_hln);
        cudaGetSymbolAddress((void**)&p_agg,  g_agg);
        cudaGetSymbolAddress((void**)&p_bw,   g_bw);
        cudaGetSymbolAddress((void**)&p_xg,   g_xg);
        cudaGetSymbolAddress((void**)&p_pert, g_pert);
        cudaGetSymbolAddress((void**)&p_h,    g_h);
        cudaGetSymbolAddress((void**)&p_z,    g_z);
        cudaGetSymbolAddress((void**)&p_t,    g_t);
        cudaGetSymbolAddress((void**)&p_part, g_part);
        cudaGetSymbolAddress((void**)&p_proj, g_proj);
        cudaGetSymbolAddress((void**)&p_deg,  g_deg);
        cudaGetSymbolAddress((void**)&p_off,  g_off);
        cudaGetSymbolAddress((void**)&p_cur,  g_cur);
        cudaGetSymbolAddress((void**)&p_bsrc, g_bsrc);
        cudaGetSymbolAddress((void**)&p_flag2, g_flag2);
        cudaGetSymbolAddress((void**)&p_flag3, g_flag3);
        cudaGetSymbolAddress((void**)&p_list2, g_list2);
        cudaGetSymbolAddress((void**)&p_list3, g_list3);
        cudaGetSymbolAddress((void**)&p_cnt2,  g_cnt2);
    }

    // ---- CSR binning of edges by dst ----
    zero_deg_kernel<<<(NNODE + 255) / 256, 256>>>(p_deg);
    hist_kernel<<<(EDGES + 255) / 256, 256>>>(edge_index, p_deg);
    scan_kernel<<<1, 1024>>>(p_deg, p_off, NNODE);
    copy_cursor_kernel<<<(NNODE + 255) / 256, 256>>>(p_off, p_cur);
    scatter_kernel<<<(EDGES + 255) / 256, 256>>>(edge_index, edge_weight, p_cur, p_bsrc, p_bw);

    // ---- frontier construction ----
    flag_init_kernel<<<(NNODE + 255) / 256, 256>>>(p_flag2, p_flag3, p_cnt2);
    flag_seed_kernel<<<1, BB>>>(node_indices, p_flag2, p_flag3, p_list3);
    flag_edge_kernel<<<(EDGES + 255) / 256, 256>>>(edge_index, p_flag3, p_flag2);
    compact_kernel<<<(NNODE + 255) / 256, 256>>>(p_flag2, p_list2, p_cnt2);

    // ---- x = partial_emb (pad rows zero) ----
    copy_x_kernel<<<(NPAD * DG + 255) / 256, 256>>>(partial_emb, p_x);

    // ---- GNN layer 0: dense ----
    ln_kernel<<<NPAD / 8, 256>>>(p_x, gnn_ln_s, gnn_ln_b, p_hln, NPAD, DG);
    agg_kernel<<<(NNODE + 7) / 8, 256>>>(p_hln, p_agg, p_off, p_bsrc, p_bw, nullptr);
    gemmx_kernel<false><<<dim3(DG / 64, NPAD / 128, 1), 128>>>(
        p_agg, gnn_w, gnn_b, p_x, p_x, nullptr, nullptr, NPAD, DG, DG, DG, EPI_RELU_RES);

    // ---- GNN layer 1: frontier F2 ----
    ln_kernel<<<NPAD / 8, 256>>>(p_x, gnn_ln_s + DG, gnn_ln_b + DG, p_hln, NPAD, DG);
    agg_kernel<<<(NNODE + 7) / 8, 256>>>(p_hln, p_agg, p_off, p_bsrc, p_bw, p_flag2);
    gemmx_kernel<false><<<dim3(DG / 64, (NNODE + 127) / 128, 1), 128>>>(
        p_agg, gnn_w + (size_t)1 * DG * DG, gnn_b + DG, p_x, p_x, p_list2, p_cnt2,
        NNODE, DG, DG, DG, EPI_RELU_RES);

    // ---- GNN layer 2: frontier F3 (batch nodes only) ----
    ln_kernel<<<NPAD / 8, 256>>>(p_x, gnn_ln_s + 2 * DG, gnn_ln_b + 2 * DG, p_hln, NPAD, DG);
    agg_kernel<<<(NNODE + 7) / 8, 256>>>(p_hln, p_agg, p_off, p_bsrc, p_bw, p_flag3);
    gemmx_kernel<false><<<dim3(DG / 64, BB / 128, 1), 128>>>(
        p_agg, gnn_w + (size_t)2 * DG * DG, gnn_b + 2 * DG, p_x, p_x, p_list3, nullptr,
        BB, DG, DG, DG, EPI_RELU_RES);

    // ---- gather 256 rows, then post_mp on just those rows ----
    gather_kernel<<<BB, DG>>>(p_x, node_indices, p_xg);
    gemmx_kernel<false><<<dim3(DG / 64, BB / 128, 1), 128>>>(
        p_xg, post_w, post_b, nullptr, p_pert, nullptr, nullptr, BB, DG, DG, DG, EPI_BIAS);
    oovfix_kernel<<<BB, DG>>>(node_indices, oov_emb, p_pert);

    // ---- proj_in ----
    gemmx_kernel<false><<<dim3(DH / 64, BB / 128, 1), 128>>>(
        p_pert, pin_w, pin_b, nullptr, p_h, nullptr, nullptr, BB, DH, DG, DG, EPI_BIAS);

    // ---- 6 residual MLP blocks ----
    for (int i = 0; i < 6; ++i) {
        ln_kernel<<<BB / 8, 256>>>(p_h, blk_ln_s + i * DH, blk_ln_b + i * DH, p_z, BB, DH);
        // t = gelu(z @ W1 + b1), split-K x4
        gemmx_kernel<false><<<dim3(DI / 64, BB / 128, 4), 128>>>(
            p_z, blk_w1 + (size_t)i * DH * DI, nullptr, nullptr, p_part, nullptr, nullptr,
            BB, DI, DH, DH / 4, EPI_NONE);
        reduce_kernel<<<(BB * DI + 255) / 256, 256>>>(p_t, p_part, blk_b1 + i * DI, 4, BB * DI, DI, 2);
        // h += t @ W2 + b2, split-K x8
        gemmx_kernel<false><<<dim3(DH / 64, BB / 128, 8), 128>>>(
            p_t, blk_w2 + (size_t)i * DI * DH, nullptr, nullptr, p_part, nullptr, nullptr,
            BB, DH, DI, DI / 8, EPI_NONE);
        reduce_kernel<<<(BB * DH + 255) / 256, 256>>>(p_h, p_part, blk_b2 + i * DH, 8, BB * DH, DH, 1);
    }

    // ---- proj_out (split-K x2) ----
    gemmx_kernel<false><<<dim3((NCLS * RNK) / 64, BB / 128, 2), 128>>>(
        p_h, pout_w, nullptr, nullptr, p_part, nullptr, nullptr, BB, NCLS * RNK, DH, DH / 2, EPI_NONE);
    reduce_kernel<<<(BB * NCLS * RNK + 255) / 256, 256>>>(p_proj, p_part, pout_b, 2, BB * NCLS * RNK, NCLS * RNK, 0);

    // ---- logits = proj[768,512] @ gene[6640,512]^T ----
    gemmx_kernel<true><<<dim3((NGENE + 63) / 64, (BB * NCLS) / 128, 1), 128>>>(
        p_proj, gene, nullptr, nullptr, out, nullptr, nullptr, BB * NCLS, NGENE, RNK, RNK, EPI_NONE);
}

// round 6
// speedup vs baseline: 1.6077x; 1.4852x over previous
#include <cuda_runtime.h>
#include <math.h>

// ---------------- problem constants ----------------
#define NNODE   20000
#define NPAD    20096          // padded to multiple of 128 for GEMM
#define EDGES   640000
#define BB      256            // batch
#define DG      256            // GNN dim
#define DH      512            // hidden
#define DI      2048           // inner
#define RNK     512
#define NCLS    3
#define NGENE   6640
#define LN_EPS  1e-5f

// ---------------- scratch (device globals; no allocation allowed) ----------------
__device__ float g_x   [NPAD * DG];
__device__ float g_hln [NPAD * DG];
__device__ float g_agg [NPAD * DG];   // pad rows never written -> stay zero
__device__ int   g_deg [NNODE];
__device__ int   g_off [NNODE + 1];
__device__ int   g_cur [NNODE];
__device__ int   g_bsrc[EDGES];
__device__ float g_bw  [EDGES];
__device__ float g_xg  [BB * DG];
__device__ float g_pert[BB * DG];
__device__ float g_h   [BB * DH];
__device__ float g_z   [BB * DH];
__device__ float g_t   [BB * DI];
__device__ float g_part[8 * BB * DI];     // split-K partials
__device__ float g_proj[BB * NCLS * RNK];
// frontier state
__device__ int   g_flag2[NNODE];
__device__ int   g_flag3[NNODE];
__device__ int   g_list2[NNODE];
__device__ int   g_list3[BB];
__device__ int   g_cnt2[1];

// ---------------- packed f32x2 helpers ----------------
__device__ __forceinline__ void ffma2(unsigned long long &d, unsigned long long a, unsigned long long b) {
    asm("fma.rn.f32x2 %0, %1, %2, %0;" : "+l"(d) : "l"(a), "l"(b));
}
__device__ __forceinline__ unsigned long long pack2(float x, float y) {
    unsigned long long r;
    asm("mov.b64 %0, {%1, %2};" : "=l"(r) : "f"(x), "f"(y));
    return r;
}
__device__ __forceinline__ float lo2(unsigned long long v) {
    return __uint_as_float((unsigned)(v & 0xffffffffull));
}
__device__ __forceinline__ float hi2(unsigned long long v) {
    return __uint_as_float((unsigned)(v >> 32));
}

// ---------------- small kernels ----------------
__global__ void zero_deg_kernel(int* deg) {
    int i = blockIdx.x * blockDim.x + threadIdx.x;
    if (i < NNODE) deg[i] = 0;
}

__global__ void hist_kernel(const int* __restrict__ ei, int* __restrict__ deg) {
    int i = blockIdx.x * blockDim.x + threadIdx.x;
    if (i < EDGES) atomicAdd(&deg[ei[EDGES + i]], 1);
}

__global__ void scan_kernel(const int* __restrict__ deg, int* __restrict__ off, int n) {
    __shared__ int sh[1024];
    __shared__ int base_s;
    int tid = threadIdx.x;
    if (tid == 0) { base_s = 0; off[0] = 0; }
    __syncthreads();
    for (int start = 0; start < n; start += 1024) {
        int v = (start + tid < n) ? deg[start + tid] : 0;
        sh[tid] = v;
        __syncthreads();
        for (int o = 1; o < 1024; o <<= 1) {
            int u = (tid >= o) ? sh[tid - o] : 0;
            __syncthreads();
            sh[tid] += u;
            __syncthreads();
        }
        if (start + tid < n) off[start + tid + 1] = base_s + sh[tid];
        int tot = sh[1023];
        __syncthreads();
        if (tid == 0) base_s += tot;
        __syncthreads();
    }
}

__global__ void copy_cursor_kernel(const int* __restrict__ off, int* __restrict__ cur) {
    int i = blockIdx.x * blockDim.x + threadIdx.x;
    if (i < NNODE) cur[i] = off[i];
}

__global__ void scatter_kernel(const int* __restrict__ ei, const float* __restrict__ ew,
                               int* __restrict__ cur, int* __restrict__ bsrc, float* __restrict__ bw) {
    int i = blockIdx.x * blockDim.x + threadIdx.x;
    if (i < EDGES) {
        int d = ei[EDGES + i];
        int p = atomicAdd(&cur[d], 1);
        bsrc[p] = ei[i];
        bw[p]   = ew[i];
    }
}

__global__ void copy_x_kernel(const float* __restrict__ src, float* __restrict__ dst) {
    int i = blockIdx.x * blockDim.x + threadIdx.x;
    if (i < NPAD * DG) dst[i] = (i < NNODE * DG) ? src[i] : 0.0f;
}

// ---- frontier kernels ----
__global__ void flag_init_kernel(int* flag2, int* flag3, int* cnt2) {
    int i = blockIdx.x * blockDim.x + threadIdx.x;
    if (i < NNODE) { flag2[i] = 0; flag3[i] = 0; }
    if (i == 0) cnt2[0] = 0;
}
__global__ void flag_seed_kernel(const int* __restrict__ idx, int* flag2, int* flag3, int* list3) {
    int i = threadIdx.x;  // BB threads
    int id = idx[i];
    int safe = id < 0 ? 0 : id;
    flag3[safe] = 1;
    flag2[safe] = 1;
    list3[i] = safe;
}
__global__ void flag_edge_kernel(const int* __restrict__ ei, const int* __restrict__ flag3,
                                 int* __restrict__ flag2) {
    int e = blockIdx.x * blockDim.x + threadIdx.x;
    if (e < EDGES && flag3[ei[EDGES + e]]) flag2[ei[e]] = 1;
}
__global__ void compact_kernel(const int* __restrict__ flag2, int* __restrict__ list2,
                               int* __restrict__ cnt2) {
    int i = blockIdx.x * blockDim.x + threadIdx.x;
    if (i < NNODE && flag2[i]) {
        int p = atomicAdd(cnt2, 1);
        list2[p] = i;
    }
}

// LayerNorm: one warp per row. D in {256, 512}. Optional row-flag skip.
__global__ void ln_kernel(const float* __restrict__ x, const float* __restrict__ s,
                          const float* __restrict__ b, float* __restrict__ y,
                          int rows, int D, const int* __restrict__ flag) {
    int wid = threadIdx.x >> 5, lane = threadIdx.x & 31;
    int row = blockIdx.x * (blockDim.x >> 5) + wid;
    if (row >= rows) return;
    if (flag && (row >= NNODE || !flag[row])) return;
    const float4* xr = (const float4*)(x + (size_t)row * D);
    int nf = D >> 7;
    float4 r[4];
    float sum = 0.f;
    for (int t = 0; t < nf; ++t) {
        r[t] = xr[lane + 32 * t];
        sum += r[t].x + r[t].y + r[t].z + r[t].w;
    }
    for (int o = 16; o > 0; o >>= 1) sum += __shfl_xor_sync(0xffffffffu, sum, o);
    float mu = sum / (float)D;
    float vs = 0.f;
    for (int t = 0; t < nf; ++t) {
        float dx = r[t].x - mu, dy = r[t].y - mu, dz = r[t].z - mu, dw = r[t].w - mu;
        vs += dx * dx + dy * dy + dz * dz + dw * dw;
    }
    for (int o = 16; o > 0; o >>= 1) vs += __shfl_xor_sync(0xffffffffu, vs, o);
    float w = rsqrtf(vs / (float)D + LN_EPS);
    float4* yr = (float4*)(y + (size_t)row * D);
    for (int t = 0; t < nf; ++t) {
        int col = (lane + 32 * t) * 4;
        float4 o4;
        o4.x = (r[t].x - mu) * w * s[col + 0] + b[col + 0];
        o4.y = (r[t].y - mu) * w * s[col + 1] + b[col + 1];
        o4.z = (r[t].z - mu) * w * s[col + 2] + b[col + 2];
        o4.w = (r[t].w - mu) * w * s[col + 3] + b[col + 3];
        yr[lane + 32 * t] = o4;
    }
}

// CSR weighted aggregation: one warp per node; optional frontier flag skip.
__global__ void agg_kernel(const float* __restrict__ hln, float* __restrict__ agg,
                           const int* __restrict__ off, const int* __restrict__ bsrc,
                           const float* __restrict__ bw, const int* __restrict__ flag) {
    int wid = threadIdx.x >> 5, lane = threadIdx.x & 31;
    int node = blockIdx.x * (blockDim.x >> 5) + wid;
    if (node >= NNODE) return;
    if (flag && !flag[node]) return;
    int st = off[node], en = off[node + 1];
    float4 a0 = make_float4(0, 0, 0, 0), a1 = make_float4(0, 0, 0, 0);
    for (int j = st; j < en; ++j) {
        int s = bsrc[j];
        float w = bw[j];
        const float4* r = (const float4*)(hln + s * DG);
        float4 v0 = r[lane], v1 = r[lane + 32];
        a0.x = fmaf(w, v0.x, a0.x); a0.y = fmaf(w, v0.y, a0.y);
        a0.z = fmaf(w, v0.z, a0.z); a0.w = fmaf(w, v0.w, a0.w);
        a1.x = fmaf(w, v1.x, a1.x); a1.y = fmaf(w, v1.y, a1.y);
        a1.z = fmaf(w, v1.z, a1.z); a1.w = fmaf(w, v1.w, a1.w);
    }
    float4* o = (float4*)(agg + node * DG);
    o[lane] = a0;
    o[lane + 32] = a1;
}

__global__ void gather_kernel(const float* __restrict__ x, const int* __restrict__ idx,
                              float* __restrict__ out) {
    int bi = blockIdx.x, j = threadIdx.x;
    int id = idx[bi];
    int safe = id < 0 ? 0 : id;
    out[bi * DG + j] = x[(size_t)safe * DG + j];
}

__global__ void oovfix_kernel(const int* __restrict__ idx, const float* __restrict__ oov_emb,
                              float* __restrict__ pert) {
    int bi = blockIdx.x, j = threadIdx.x;
    if (idx[bi] < 0) pert[bi * DG + j] = oov_emb[j];
}

// Split-K reduce with epilogue.
// mode 0: dst = bias + sum ; mode 1: dst += bias + sum ; mode 2: dst = gelu(bias + sum)
__global__ void reduce_kernel(float* __restrict__ dst, const float* __restrict__ part,
                              const float* __restrict__ bias, int S, int total, int N, int mode) {
    int i = blockIdx.x * blockDim.x + threadIdx.x;
    if (i >= total) return;
    float v = bias[i % N];
    for (int z = 0; z < S; ++z) v += part[(size_t)z * total + i];
    if (mode == 2) v = 0.5f * v * (1.f + erff(v * 0.70710678118654752f));
    if (mode == 1) dst[i] += v;
    else           dst[i] = v;
}

// ---------------- GEMM (R2-proven): 128x64 tile, BK=16, 128 threads, 8x8 microtile (f32x2)
enum { EPI_NONE = 0, EPI_BIAS = 1, EPI_RELU_RES = 2 };

template <bool BT>   // BT=false: B row-major [K,N];  BT=true: B row-major [N,K] (C = A @ B^T)
__global__ void __launch_bounds__(128) gemmx_kernel(
    const float* __restrict__ A, const float* __restrict__ B,
    const float* __restrict__ bias, const float* __restrict__ res,
    float* __restrict__ C, int M, int N, int K, int kChunk, int epi)
{
    __shared__ float As[16][132];   // [k][m], m-pairs 8B aligned
    __shared__ float Bs[16][68];    // [k][n]
    int t  = threadIdx.x;
    int m0 = blockIdx.y * 128;
    int n0 = blockIdx.x * 64;
    int ks = blockIdx.z * kChunk;
    int ke = ks + kChunk; if (ke > K) ke = K;

    int tx8 = (t & 7) * 8;     // n offset within tile
    int ty8 = (t >> 3) * 8;    // m offset within tile

    unsigned long long acc[4][8];
#pragma unroll
    for (int p = 0; p < 4; ++p)
#pragma unroll
        for (int j = 0; j < 8; ++j) acc[p][j] = 0ull;

    for (int k0 = ks; k0 < ke; k0 += 16) {
        // A tile: 128 rows x 16 k, transpose into As[k][m]
#pragma unroll
        for (int j = 0; j < 4; ++j) {
            int f = j * 128 + t;
            int row = f >> 2;          // 0..127
            int kc  = (f & 3) << 2;    // 0,4,8,12
            int gm  = m0 + row;
            float4 v = make_float4(0, 0, 0, 0);
            if (gm < M) v = *(const float4*)(A + (size_t)gm * K + k0 + kc);
            As[kc + 0][row] = v.x; As[kc + 1][row] = v.y;
            As[kc + 2][row] = v.z; As[kc + 3][row] = v.w;
        }
        // B tile: 16 k x 64 n
        if (!BT) {
#pragma unroll
            for (int j = 0; j < 2; ++j) {
                int f = j * 128 + t;
                int kr = f >> 4;           // 0..15
                int nc = (f & 15) << 2;    // 0..60
                int gn = n0 + nc;
                float4 v = make_float4(0, 0, 0, 0);
                if (gn < N) v = *(const float4*)(B + (size_t)(k0 + kr) * N + gn);
                *(float4*)&Bs[kr][nc] = v;
            }
        } else {
#pragma unroll
            for (int j = 0; j < 2; ++j) {
                int f = j * 128 + t;
                int row = f >> 2;          // 0..63 (n)
                int kc  = (f & 3) << 2;
                int gn  = n0 + row;
                float4 v = make_float4(0, 0, 0, 0);
                if (gn < N) v = *(const float4*)(B + (size_t)gn * K + k0 + kc);
                Bs[kc + 0][row] = v.x; Bs[kc + 1][row] = v.y;
                Bs[kc + 2][row] = v.z; Bs[kc + 3][row] = v.w;
            }
        }
        __syncthreads();
#pragma unroll
        for (int kk = 0; kk < 16; ++kk) {
            const float* Ar = &As[kk][ty8];
            unsigned long long a0 = *(const unsigned long long*)(Ar + 0);
            unsigned long long a1 = *(const unsigned long long*)(Ar + 2);
            unsigned long long a2 = *(const unsigned long long*)(Ar + 4);
            unsigned long long a3 = *(const unsigned long long*)(Ar + 6);
            float4 b0 = *(const float4*)&Bs[kk][tx8];
            float4 b1 = *(const float4*)&Bs[kk][tx8 + 4];
            unsigned long long bd[8];
            bd[0] = pack2(b0.x, b0.x); bd[1] = pack2(b0.y, b0.y);
            bd[2] = pack2(b0.z, b0.z); bd[3] = pack2(b0.w, b0.w);
            bd[4] = pack2(b1.x, b1.x); bd[5] = pack2(b1.y, b1.y);
            bd[6] = pack2(b1.z, b1.z); bd[7] = pack2(b1.w, b1.w);
#pragma unroll
            for (int j = 0; j < 8; ++j) {
                ffma2(acc[0][j], a0, bd[j]);
                ffma2(acc[1][j], a1, bd[j]);
                ffma2(acc[2][j], a2, bd[j]);
                ffma2(acc[3][j], a3, bd[j]);
            }
        }
        __syncthreads();
    }

    float* Cz = C + (size_t)blockIdx.z * M * N;
    bool nfull = (n0 + 64 <= N);
#pragma unroll
    for (int p = 0; p < 4; ++p) {
#pragma unroll
        for (int h = 0; h < 2; ++h) {
            int gm = m0 + ty8 + 2 * p + h;
            if (gm >= M) continue;
            float v[8];
#pragma unroll
            for (int j = 0; j < 8; ++j) v[j] = h ? hi2(acc[p][j]) : lo2(acc[p][j]);
            int gn0 = n0 + tx8;
            if (epi == EPI_RELU_RES) {
                const float4 r0 = *(const float4*)(res + (size_t)gm * N + gn0);
                const float4 r1 = *(const float4*)(res + (size_t)gm * N + gn0 + 4);
#pragma unroll
                for (int j = 0; j < 8; ++j) {
                    float bi = bias[gn0 + j];
                    float rr = (j < 4) ? ((const float*)&r0)[j] : ((const float*)&r1)[j - 4];
                    v[j] = fmaxf(v[j] + bi, 0.f) + rr;
                }
            } else if (epi == EPI_BIAS) {
#pragma unroll
                for (int j = 0; j < 8; ++j) v[j] += bias[gn0 + j];
            }
            if (nfull) {
                float4 o0 = make_float4(v[0], v[1], v[2], v[3]);
                float4 o1 = make_float4(v[4], v[5], v[6], v[7]);
                *(float4*)(Cz + (size_t)gm * N + gn0)     = o0;
                *(float4*)(Cz + (size_t)gm * N + gn0 + 4) = o1;
            } else {
#pragma unroll
                for (int j = 0; j < 8; ++j)
                    if (gn0 + j < N) Cz[(size_t)gm * N + gn0 + j] = v[j];
            }
        }
    }
}

// Row-list GEMM variant (frontier layers only): C[rows[m]] = relu(A[rows[m]] @ B + bias) + res[rows[m]]
__global__ void __launch_bounds__(128) gemmg_kernel(
    const float* __restrict__ A, const float* __restrict__ B,
    const float* __restrict__ bias, const float* __restrict__ res,
    float* __restrict__ C, const int* __restrict__ rows, const int* __restrict__ cntp,
    int Mmax, int N, int K)
{
    __shared__ float As[16][132];
    __shared__ float Bs[16][68];
    int Meff = cntp ? *cntp : Mmax;
    int t  = threadIdx.x;
    int m0 = blockIdx.y * 128;
    if (m0 >= Meff) return;
    int n0 = blockIdx.x * 64;

    int tx8 = (t & 7) * 8;
    int ty8 = (t >> 3) * 8;

    unsigned long long acc[4][8];
#pragma unroll
    for (int p = 0; p < 4; ++p)
#pragma unroll
        for (int j = 0; j < 8; ++j) acc[p][j] = 0ull;

    for (int k0 = 0; k0 < K; k0 += 16) {
#pragma unroll
        for (int j = 0; j < 4; ++j) {
            int f = j * 128 + t;
            int row = f >> 2;
            int kc  = (f & 3) << 2;
            int lm  = m0 + row;
            float4 v = make_float4(0, 0, 0, 0);
            if (lm < Meff) {
                int gr = rows[lm];
                v = *(const float4*)(A + (size_t)gr * K + k0 + kc);
            }
            As[kc + 0][row] = v.x; As[kc + 1][row] = v.y;
            As[kc + 2][row] = v.z; As[kc + 3][row] = v.w;
        }
#pragma unroll
        for (int j = 0; j < 2; ++j) {
            int f = j * 128 + t;
            int kr = f >> 4;
            int nc = (f & 15) << 2;
            int gn = n0 + nc;
            float4 v = make_float4(0, 0, 0, 0);
            if (gn < N) v = *(const float4*)(B + (size_t)(k0 + kr) * N + gn);
            *(float4*)&Bs[kr][nc] = v;
        }
        __syncthreads();
#pragma unroll
        for (int kk = 0; kk < 16; ++kk) {
            const float* Ar = &As[kk][ty8];
            unsigned long long a0 = *(const unsigned long long*)(Ar + 0);
            unsigned long long a1 = *(const unsigned long long*)(Ar + 2);
            unsigned long long a2 = *(const unsigned long long*)(Ar + 4);
            unsigned long long a3 = *(const unsigned long long*)(Ar + 6);
            float4 b0 = *(const float4*)&Bs[kk][tx8];
            float4 b1 = *(const float4*)&Bs[kk][tx8 + 4];
            unsigned long long bd[8];
            bd[0] = pack2(b0.x, b0.x); bd[1] = pack2(b0.y, b0.y);
            bd[2] = pack2(b0.z, b0.z); bd[3] = pack2(b0.w, b0.w);
            bd[4] = pack2(b1.x, b1.x); bd[5] = pack2(b1.y, b1.y);
            bd[6] = pack2(b1.z, b1.z); bd[7] = pack2(b1.w, b1.w);
#pragma unroll
            for (int j = 0; j < 8; ++j) {
                ffma2(acc[0][j], a0, bd[j]);
                ffma2(acc[1][j], a1, bd[j]);
                ffma2(acc[2][j], a2, bd[j]);
                ffma2(acc[3][j], a3, bd[j]);
            }
        }
        __syncthreads();
    }

#pragma unroll
    for (int p = 0; p < 4; ++p) {
#pragma unroll
        for (int h = 0; h < 2; ++h) {
            int lm = m0 + ty8 + 2 * p + h;
            if (lm >= Meff) continue;
            int gr = rows[lm];
            float v[8];
#pragma unroll
            for (int j = 0; j < 8; ++j) v[j] = h ? hi2(acc[p][j]) : lo2(acc[p][j]);
            int gn0 = n0 + tx8;
#pragma unroll
            for (int j = 0; j < 8; ++j) {
                float bi = bias[gn0 + j];
                float rr = res[(size_t)gr * N + gn0 + j];
                v[j] = fmaxf(v[j] + bi, 0.f) + rr;
            }
            *(float4*)(C + (size_t)gr * N + gn0)     = make_float4(v[0], v[1], v[2], v[3]);
            *(float4*)(C + (size_t)gr * N + gn0 + 4) = make_float4(v[4], v[5], v[6], v[7]);
        }
    }
}

// ---------------- launch ----------------
extern "C" void kernel_launch(void* const* d_in, const int* in_sizes, int n_in,
                              void* d_out, int out_size) {
    const int*   node_indices = (const int*)d_in[0];
    const int*   edge_index   = (const int*)d_in[1];
    const float* edge_weight  = (const float*)d_in[2];
    const float* partial_emb  = (const float*)d_in[3];
    const float* oov_emb      = (const float*)d_in[4];
    const float* gnn_ln_s     = (const float*)d_in[5];
    const float* gnn_ln_b     = (const float*)d_in[6];
    const float* gnn_w        = (const float*)d_in[7];
    const float* gnn_b        = (const float*)d_in[8];
    const float* post_w       = (const float*)d_in[9];
    const float* post_b       = (const float*)d_in[10];
    const float* pin_w        = (const float*)d_in[11];
    const float* pin_b        = (const float*)d_in[12];
    const float* blk_ln_s     = (const float*)d_in[13];
    const float* blk_ln_b     = (const float*)d_in[14];
    const float* blk_w1       = (const float*)d_in[15];
    const float* blk_b1       = (const float*)d_in[16];
    const float* blk_w2       = (const float*)d_in[17];
    const float* blk_b2       = (const float*)d_in[18];
    const float* pout_w       = (const float*)d_in[19];
    const float* pout_b       = (const float*)d_in[20];
    const float* gene         = (const float*)d_in[21];
    float*       out          = (float*)d_out;

    static float *p_x = nullptr, *p_hln, *p_agg, *p_bw, *p_xg, *p_pert, *p_h, *p_z, *p_t, *p_part, *p_proj;
    static int   *p_deg, *p_off, *p_cur, *p_bsrc;
    static int   *p_flag2, *p_flag3, *p_list2, *p_list3, *p_cnt2;
    if (!p_x) {
        cudaGetSymbolAddress((void**)&p_x,    g_x);
        cudaGetSymbolAddress((void**)&p_hln,  g_hln);
        cudaGetSymbolAddress((void**)&p_agg,  g_agg);
        cudaGetSymbolAddress((void**)&p_bw,   g_bw);
        cudaGetSymbolAddress((void**)&p_xg,   g_xg);
        cudaGetSymbolAddress((void**)&p_pert, g_pert);
        cudaGetSymbolAddress((void**)&p_h,    g_h);
        cudaGetSymbolAddress((void**)&p_z,    g_z);
        cudaGetSymbolAddress((void**)&p_t,    g_t);
        cudaGetSymbolAddress((void**)&p_part, g_part);
        cudaGetSymbolAddress((void**)&p_proj, g_proj);
        cudaGetSymbolAddress((void**)&p_deg,  g_deg);
        cudaGetSymbolAddress((void**)&p_off,  g_off);
        cudaGetSymbolAddress((void**)&p_cur,  g_cur);
        cudaGetSymbolAddress((void**)&p_bsrc, g_bsrc);
        cudaGetSymbolAddress((void**)&p_flag2, g_flag2);
        cudaGetSymbolAddress((void**)&p_flag3, g_flag3);
        cudaGetSymbolAddress((void**)&p_list2, g_list2);
        cudaGetSymbolAddress((void**)&p_list3, g_list3);
        cudaGetSymbolAddress((void**)&p_cnt2,  g_cnt2);
    }

    // ---- CSR binning of edges by dst ----
    zero_deg_kernel<<<(NNODE + 255) / 256, 256>>>(p_deg);
    hist_kernel<<<(EDGES + 255) / 256, 256>>>(edge_index, p_deg);
    scan_kernel<<<1, 1024>>>(p_deg, p_off, NNODE);
    copy_cursor_kernel<<<(NNODE + 255) / 256, 256>>>(p_off, p_cur);
    scatter_kernel<<<(EDGES + 255) / 256, 256>>>(edge_index, edge_weight, p_cur, p_bsrc, p_bw);

    // ---- frontier construction ----
    flag_init_kernel<<<(NNODE + 255) / 256, 256>>>(p_flag2, p_flag3, p_cnt2);
    flag_seed_kernel<<<1, BB>>>(node_indices, p_flag2, p_flag3, p_list3);
    flag_edge_kernel<<<(EDGES + 255) / 256, 256>>>(edge_index, p_flag3, p_flag2);
    compact_kernel<<<(NNODE + 255) / 256, 256>>>(p_flag2, p_list2, p_cnt2);

    // ---- x = partial_emb (pad rows zero) ----
    copy_x_kernel<<<(NPAD * DG + 255) / 256, 256>>>(partial_emb, p_x);

    // ---- GNN layer 0: dense (R2-proven GEMM) ----
    ln_kernel<<<NPAD / 8, 256>>>(p_x, gnn_ln_s, gnn_ln_b, p_hln, NPAD, DG, nullptr);
    agg_kernel<<<(NNODE + 7) / 8, 256>>>(p_hln, p_agg, p_off, p_bsrc, p_bw, nullptr);
    gemmx_kernel<false><<<dim3(DG / 64, NPAD / 128, 1), 128>>>(
        p_agg, gnn_w, gnn_b, p_x, p_x, NPAD, DG, DG, DG, EPI_RELU_RES);

    // ---- GNN layer 1: frontier F2 (row-list GEMM) ----
    ln_kernel<<<NPAD / 8, 256>>>(p_x, gnn_ln_s + DG, gnn_ln_b + DG, p_hln, NPAD, DG, nullptr);
    agg_kernel<<<(NNODE + 7) / 8, 256>>>(p_hln, p_agg, p_off, p_bsrc, p_bw, p_flag2);
    gemmg_kernel<<<dim3(DG / 64, (NNODE + 127) / 128), 128>>>(
        p_agg, gnn_w + (size_t)1 * DG * DG, gnn_b + DG, p_x, p_x, p_list2, p_cnt2,
        NNODE, DG, DG);

    // ---- GNN layer 2: frontier F3 (LN restricted to F2 rows; batch nodes only) ----
    ln_kernel<<<NPAD / 8, 256>>>(p_x, gnn_ln_s + 2 * DG, gnn_ln_b + 2 * DG, p_hln, NPAD, DG, p_flag2);
    agg_kernel<<<(NNODE + 7) / 8, 256>>>(p_hln, p_agg, p_off, p_bsrc, p_bw, p_flag3);
    gemmg_kernel<<<dim3(DG / 64, BB / 128), 128>>>(
        p_agg, gnn_w + (size_t)2 * DG * DG, gnn_b + 2 * DG, p_x, p_x, p_list3, nullptr,
        BB, DG, DG);

    // ---- gather 256 rows, then post_mp on just those rows ----
    gather_kernel<<<BB, DG>>>(p_x, node_indices, p_xg);
    gemmx_kernel<false><<<dim3(DG / 64, BB / 128, 1), 128>>>(
        p_xg, post_w, post_b, nullptr, p_pert, BB, DG, DG, DG, EPI_BIAS);
    oovfix_kernel<<<BB, DG>>>(node_indices, oov_emb, p_pert);

    // ---- proj_in ----
    gemmx_kernel<false><<<dim3(DH / 64, BB / 128, 1), 128>>>(
        p_pert, pin_w, pin_b, nullptr, p_h, BB, DH, DG, DG, EPI_BIAS);

    // ---- 6 residual MLP blocks ----
    for (int i = 0; i < 6; ++i) {
        ln_kernel<<<BB / 8, 256>>>(p_h, blk_ln_s + i * DH, blk_ln_b + i * DH, p_z, BB, DH, nullptr);
        // t = gelu(z @ W1 + b1), split-K x4
        gemmx_kernel<false><<<dim3(DI / 64, BB / 128, 4), 128>>>(
            p_z, blk_w1 + (size_t)i * DH * DI, nullptr, nullptr, p_part,
            BB, DI, DH, DH / 4, EPI_NONE);
        reduce_kernel<<<(BB * DI + 255) / 256, 256>>>(p_t, p_part, blk_b1 + i * DI, 4, BB * DI, DI, 2);
        // h += t @ W2 + b2, split-K x8
        gemmx_kernel<false><<<dim3(DH / 64, BB / 128, 8), 128>>>(
            p_t, blk_w2 + (size_t)i * DI * DH, nullptr, nullptr, p_part,
            BB, DH, DI, DI / 8, EPI_NONE);
        reduce_kernel<<<(BB * DH + 255) / 256, 256>>>(p_h, p_part, blk_b2 + i * DH, 8, BB * DH, DH, 1);
    }

    // ---- proj_out (split-K x2) ----
    gemmx_kernel<false><<<dim3((NCLS * RNK) / 64, BB / 128, 2), 128>>>(
        p_h, pout_w, nullptr, nullptr, p_part, BB, NCLS * RNK, DH, DH / 2, EPI_NONE);
    reduce_kernel<<<(BB * NCLS * RNK + 255) / 256, 256>>>(p_proj, p_part, pout_b, 2, BB * NCLS * RNK, NCLS * RNK, 0);

    // ---- logits = proj[768,512] @ gene[6640,512]^T ----
    gemmx_kernel<true><<<dim3((NGENE + 63) / 64, (BB * NCLS) / 128, 1), 128>>>(
        p_proj, gene, nullptr, nullptr, out, BB * NCLS, NGENE, RNK, RNK, EPI_NONE);
}

// round 7
// speedup vs baseline: 1.9216x; 1.1952x over previous
#include <cuda_runtime.h>
#include <math.h>
#include <stdint.h>

// ---------------- problem constants ----------------
#define NNODE   20000
#define NPAD    20096          // multiple of 128
#define EDGES   640000
#define BB      256
#define DG      256
#define DH      512
#define DI      2048
#define RNK     512
#define NCLS    3
#define NGENE   6640
#define NGENE_PAD 6656         // multiple of 64
#define LN_EPS  1e-5f

// ---------------- scratch (device globals) ----------------
__device__ float g_x   [NPAD * DG];
__device__ float g_hln [NPAD * DG];
__device__ float g_agg [NPAD * DG];
__device__ int   g_deg [NNODE];
__device__ int   g_off [NNODE + 1];
__device__ int   g_cur [NNODE];
__device__ int   g_bsrc[EDGES];
__device__ float g_bw  [EDGES];
__device__ float g_xg  [BB * DG];
__device__ float g_pert[BB * DG];
__device__ float g_h   [BB * DH];
__device__ float g_z   [BB * DH];
__device__ float g_t   [BB * DI];
__device__ float g_part[8 * BB * DI];
__device__ float g_proj[BB * NCLS * RNK];
__device__ float g_geneT[RNK * NGENE_PAD];   // gene transposed [RNK][NGENE_PAD], zero-padded
// frontier state
__device__ int   g_flag2[NNODE];
__device__ int   g_flag3[NNODE];
__device__ int   g_list2[NNODE];
__device__ int   g_list3[BB];
__device__ int   g_cnt2[1];

// ---------------- packed f32x2 + cp.async helpers ----------------
__device__ __forceinline__ void ffma2(unsigned long long &d, unsigned long long a, unsigned long long b) {
    asm("fma.rn.f32x2 %0, %1, %2, %0;" : "+l"(d) : "l"(a), "l"(b));
}
__device__ __forceinline__ unsigned long long pack2(float x, float y) {
    unsigned long long r;
    asm("mov.b64 %0, {%1, %2};" : "=l"(r) : "f"(x), "f"(y));
    return r;
}
__device__ __forceinline__ float lo2(unsigned long long v) {
    return __uint_as_float((unsigned)(v & 0xffffffffull));
}
__device__ __forceinline__ float hi2(unsigned long long v) {
    return __uint_as_float((unsigned)(v >> 32));
}
__device__ __forceinline__ uint32_t smem_u32(const void* p) {
    uint32_t a;
    asm("{ .reg .u64 t; cvta.to.shared.u64 t, %1; cvt.u32.u64 %0, t; }" : "=r"(a) : "l"(p));
    return a;
}
#define CP_ASYNC16(dst, src) \
    asm volatile("cp.async.cg.shared.global [%0], [%1], 16;" :: "r"(dst), "l"(src))
#define CP_COMMIT() asm volatile("cp.async.commit_group;" ::: "memory")
#define CP_WAIT1()  asm volatile("cp.async.wait_group 1;" ::: "memory")
#define CP_WAIT0()  asm volatile("cp.async.wait_group 0;" ::: "memory")

// ---------------- small kernels ----------------
__global__ void zero_deg_kernel(int* deg) {
    int i = blockIdx.x * blockDim.x + threadIdx.x;
    if (i < NNODE) deg[i] = 0;
}
__global__ void hist_kernel(const int* __restrict__ ei, int* __restrict__ deg) {
    int i = blockIdx.x * blockDim.x + threadIdx.x;
    if (i < EDGES) atomicAdd(&deg[ei[EDGES + i]], 1);
}
__global__ void scan_kernel(const int* __restrict__ deg, int* __restrict__ off, int n) {
    __shared__ int sh[1024];
    __shared__ int base_s;
    int tid = threadIdx.x;
    if (tid == 0) { base_s = 0; off[0] = 0; }
    __syncthreads();
    for (int start = 0; start < n; start += 1024) {
        int v = (start + tid < n) ? deg[start + tid] : 0;
        sh[tid] = v;
        __syncthreads();
        for (int o = 1; o < 1024; o <<= 1) {
            int u = (tid >= o) ? sh[tid - o] : 0;
            __syncthreads();
            sh[tid] += u;
            __syncthreads();
        }
        if (start + tid < n) off[start + tid + 1] = base_s + sh[tid];
        int tot = sh[1023];
        __syncthreads();
        if (tid == 0) base_s += tot;
        __syncthreads();
    }
}
__global__ void copy_cursor_kernel(const int* __restrict__ off, int* __restrict__ cur) {
    int i = blockIdx.x * blockDim.x + threadIdx.x;
    if (i < NNODE) cur[i] = off[i];
}
__global__ void scatter_kernel(const int* __restrict__ ei, const float* __restrict__ ew,
                               int* __restrict__ cur, int* __restrict__ bsrc, float* __restrict__ bw) {
    int i = blockIdx.x * blockDim.x + threadIdx.x;
    if (i < EDGES) {
        int d = ei[EDGES + i];
        int p = atomicAdd(&cur[d], 1);
        bsrc[p] = ei[i];
        bw[p]   = ew[i];
    }
}
__global__ void copy_x_kernel(const float* __restrict__ src, float* __restrict__ dst) {
    int i = blockIdx.x * blockDim.x + threadIdx.x;
    if (i < NPAD * DG) dst[i] = (i < NNODE * DG) ? src[i] : 0.0f;
}
// gene transpose: [NGENE][RNK] -> [RNK][NGENE_PAD] (zero-padded cols)
__global__ void tgene_kernel(const float* __restrict__ g, float* __restrict__ gt) {
    __shared__ float tb[32][33];
    int n0 = blockIdx.x * 32, r0 = blockIdx.y * 32;
    int tx = threadIdx.x, ty = threadIdx.y;   // 32 x 8
    for (int dy = 0; dy < 32; dy += 8) {
        int n = n0 + ty + dy;
        tb[ty + dy][tx] = (n < NGENE) ? g[(size_t)n * RNK + r0 + tx] : 0.f;
    }
    __syncthreads();
    for (int dy = 0; dy < 32; dy += 8)
        gt[(size_t)(r0 + ty + dy) * NGENE_PAD + n0 + tx] = tb[tx][ty + dy];
}
// ---- frontier kernels ----
__global__ void flag_init_kernel(int* flag2, int* flag3, int* cnt2) {
    int i = blockIdx.x * blockDim.x + threadIdx.x;
    if (i < NNODE) { flag2[i] = 0; flag3[i] = 0; }
    if (i == 0) cnt2[0] = 0;
}
__global__ void flag_seed_kernel(const int* __restrict__ idx, int* flag2, int* flag3, int* list3) {
    int i = threadIdx.x;
    int id = idx[i];
    int safe = id < 0 ? 0 : id;
    flag3[safe] = 1;
    flag2[safe] = 1;
    list3[i] = safe;
}
__global__ void flag_edge_kernel(const int* __restrict__ ei, const int* __restrict__ flag3,
                                 int* __restrict__ flag2) {
    int e = blockIdx.x * blockDim.x + threadIdx.x;
    if (e < EDGES && flag3[ei[EDGES + e]]) flag2[ei[e]] = 1;
}
__global__ void compact_kernel(const int* __restrict__ flag2, int* __restrict__ list2,
                               int* __restrict__ cnt2) {
    int i = blockIdx.x * blockDim.x + threadIdx.x;
    if (i < NNODE && flag2[i]) {
        int p = atomicAdd(cnt2, 1);
        list2[p] = i;
    }
}
// LayerNorm: one warp per row; optional row-flag skip.
__global__ void ln_kernel(const float* __restrict__ x, const float* __restrict__ s,
                          const float* __restrict__ b, float* __restrict__ y,
                          int rows, int D, const int* __restrict__ flag) {
    int wid = threadIdx.x >> 5, lane = threadIdx.x & 31;
    int row = blockIdx.x * (blockDim.x >> 5) + wid;
    if (row >= rows) return;
    if (flag && (row >= NNODE || !flag[row])) return;
    const float4* xr = (const float4*)(x + (size_t)row * D);
    int nf = D >> 7;
    float4 r[4];
    float sum = 0.f;
    for (int t = 0; t < nf; ++t) {
        r[t] = xr[lane + 32 * t];
        sum += r[t].x + r[t].y + r[t].z + r[t].w;
    }
    for (int o = 16; o > 0; o >>= 1) sum += __shfl_xor_sync(0xffffffffu, sum, o);
    float mu = sum / (float)D;
    float vs = 0.f;
    for (int t = 0; t < nf; ++t) {
        float dx = r[t].x - mu, dy = r[t].y - mu, dz = r[t].z - mu, dw = r[t].w - mu;
        vs += dx * dx + dy * dy + dz * dz + dw * dw;
    }
    for (int o = 16; o > 0; o >>= 1) vs += __shfl_xor_sync(0xffffffffu, vs, o);
    float w = rsqrtf(vs / (float)D + LN_EPS);
    float4* yr = (float4*)(y + (size_t)row * D);
    for (int t = 0; t < nf; ++t) {
        int col = (lane + 32 * t) * 4;
        float4 o4;
        o4.x = (r[t].x - mu) * w * s[col + 0] + b[col + 0];
        o4.y = (r[t].y - mu) * w * s[col + 1] + b[col + 1];
        o4.z = (r[t].z - mu) * w * s[col + 2] + b[col + 2];
        o4.w = (r[t].w - mu) * w * s[col + 3] + b[col + 3];
        yr[lane + 32 * t] = o4;
    }
}
// CSR weighted aggregation: one warp per node; optional frontier flag skip.
__global__ void agg_kernel(const float* __restrict__ hln, float* __restrict__ agg,
                           const int* __restrict__ off, const int* __restrict__ bsrc,
                           const float* __restrict__ bw, const int* __restrict__ flag) {
    int wid = threadIdx.x >> 5, lane = threadIdx.x & 31;
    int node = blockIdx.x * (blockDim.x >> 5) + wid;
    if (node >= NNODE) return;
    if (flag && !flag[node]) return;
    int st = off[node], en = off[node + 1];
    float4 a0 = make_float4(0, 0, 0, 0), a1 = make_float4(0, 0, 0, 0);
    for (int j = st; j < en; ++j) {
        int s = bsrc[j];
        float w = bw[j];
        const float4* r = (const float4*)(hln + s * DG);
        float4 v0 = r[lane], v1 = r[lane + 32];
        a0.x = fmaf(w, v0.x, a0.x); a0.y = fmaf(w, v0.y, a0.y);
        a0.z = fmaf(w, v0.z, a0.z); a0.w = fmaf(w, v0.w, a0.w);
        a1.x = fmaf(w, v1.x, a1.x); a1.y = fmaf(w, v1.y, a1.y);
        a1.z = fmaf(w, v1.z, a1.z); a1.w = fmaf(w, v1.w, a1.w);
    }
    float4* o = (float4*)(agg + node * DG);
    o[lane] = a0;
    o[lane + 32] = a1;
}
__global__ void gather_kernel(const float* __restrict__ x, const int* __restrict__ idx,
                              float* __restrict__ out) {
    int bi = blockIdx.x, j = threadIdx.x;
    int id = idx[bi];
    int safe = id < 0 ? 0 : id;
    out[bi * DG + j] = x[(size_t)safe * DG + j];
}
__global__ void oovfix_kernel(const int* __restrict__ idx, const float* __restrict__ oov_emb,
                              float* __restrict__ pert) {
    int bi = blockIdx.x, j = threadIdx.x;
    if (idx[bi] < 0) pert[bi * DG + j] = oov_emb[j];
}
// Split-K reduce. mode 0: dst = b + sum ; 1: dst += b + sum ; 2: dst = gelu(b + sum)
__global__ void reduce_kernel(float* __restrict__ dst, const float* __restrict__ part,
                              const float* __restrict__ bias, int S, int total, int N, int mode) {
    int i = blockIdx.x * blockDim.x + threadIdx.x;
    if (i >= total) return;
    float v = bias[i % N];
    for (int z = 0; z < S; ++z) v += part[(size_t)z * total + i];
    if (mode == 2) v = 0.5f * v * (1.f + erff(v * 0.70710678118654752f));
    if (mode == 1) dst[i] += v;
    else           dst[i] = v;
}

// ---------------- GEMM: cp.async 3-stage pipeline, 128x64 tile, BK=16, 128 thr, f32x2 ----
// A[m][k] SMEM (chunk-swizzled), B[k][n] SMEM. acc pairs along n.
// C[M,Nout] = A[M,K] @ B[K,Nb]  (Nb >= Nout, both cols of B in-bounds/padded)
enum { EPI_NONE = 0, EPI_BIAS = 1, EPI_RELU_RES = 2 };

template <bool GATHER>
__global__ void __launch_bounds__(128) gemmp_kernel(
    const float* __restrict__ A, const float* __restrict__ B,
    const float* __restrict__ bias, const float* __restrict__ res,
    float* __restrict__ C, const int* __restrict__ rows, const int* __restrict__ cntp,
    int M, int Nb, int Nout, int K, int kChunk, int epi)
{
    __shared__ __align__(16) float As[3][128][16];
    __shared__ __align__(16) float Bs[3][16][64];
    int Meff = (GATHER && cntp) ? *cntp : M;
    int t = threadIdx.x;
    int m0 = blockIdx.y * 128;
    if (m0 >= Meff) return;
    int n0 = blockIdx.x * 64;
    int ks = blockIdx.z * kChunk;
    int ke = ks + kChunk; if (ke > K) ke = K;
    int nkb = (ke - ks) >> 4;

    uint32_t sA = smem_u32(As);
    uint32_t sB = smem_u32(Bs);

    // A-load geometry: 4 chunks/thread
    int mj0 = t >> 2, cA = t & 3;
    const float* aSrc[4];
    uint32_t aDst[4];
#pragma unroll
    for (int j = 0; j < 4; ++j) {
        int ml = 32 * j + mj0;
        int lm = m0 + ml;
        int gm;
        if (GATHER) gm = rows[lm < Meff ? lm : 0];
        else        gm = (lm < M) ? lm : 0;
        aSrc[j] = A + (size_t)gm * K + ks + 4 * cA;
        int cs = cA ^ ((ml >> 3) & 3);
        aDst[j] = sA + (uint32_t)(ml * 64 + cs * 16);
    }
    // B-load geometry: 2 chunks/thread
    const float* bSrc[2];
    uint32_t bDst[2];
#pragma unroll
    for (int j = 0; j < 2; ++j) {
        int id = t + 128 * j;
        int kr = id >> 4, cb = id & 15;
        bSrc[j] = B + (size_t)(ks + kr) * Nb + n0 + 4 * cb;
        bDst[j] = sB + (uint32_t)(kr * 256 + cb * 16);
    }

    unsigned long long acc[8][4];
#pragma unroll
    for (int i = 0; i < 8; ++i)
#pragma unroll
        for (int j = 0; j < 4; ++j) acc[i][j] = 0ull;

    int gtw = (t >> 3) & 3;
    int ty8 = (t >> 3) * 8, tx8 = (t & 7) * 8;
    int fo[4];
#pragma unroll
    for (int c = 0; c < 4; ++c) fo[c] = 4 * (c ^ gtw);

    // prologue: stages 0,1
    {
#pragma unroll
        for (int j = 0; j < 4; ++j) CP_ASYNC16(aDst[j], aSrc[j]);
#pragma unroll
        for (int j = 0; j < 2; ++j) CP_ASYNC16(bDst[j], bSrc[j]);
        CP_COMMIT();
        if (nkb > 1) {
#pragma unroll
            for (int j = 0; j < 4; ++j) CP_ASYNC16(aDst[j] + 8192u, aSrc[j] + 16);
#pragma unroll
            for (int j = 0; j < 2; ++j) CP_ASYNC16(bDst[j] + 4096u, bSrc[j] + (size_t)16 * Nb);
            CP_COMMIT();
        }
    }

    for (int i = 0; i < nkb; ++i) {
        if (i + 1 < nkb) { CP_WAIT1(); } else { CP_WAIT0(); }
        __syncthreads();
        int nx = i + 2;
        if (nx < nkb) {
            int st = nx % 3;
            uint32_t so = (uint32_t)st * 8192u, sob = (uint32_t)st * 4096u;
            int kof = nx << 4;
#pragma unroll
            for (int j = 0; j < 4; ++j) CP_ASYNC16(aDst[j] + so, aSrc[j] + kof);
#pragma unroll
            for (int j = 0; j < 2; ++j) CP_ASYNC16(bDst[j] + sob, bSrc[j] + (size_t)kof * Nb);
            CP_COMMIT();
        }
        int s = i % 3;
        const float (*Asr)[16] = As[s];
        const float (*Bsr)[64] = Bs[s];
#pragma unroll
        for (int kk = 0; kk < 16; ++kk) {
            int fs = fo[kk >> 2] + (kk & 3);
            unsigned long long ad[8], bd[4];
#pragma unroll
            for (int i8 = 0; i8 < 8; ++i8) {
                float av = Asr[ty8 + i8][fs];
                ad[i8] = pack2(av, av);
            }
#pragma unroll
            for (int j = 0; j < 4; ++j)
                bd[j] = *(const unsigned long long*)&Bsr[kk][tx8 + 2 * j];
#pragma unroll
            for (int i8 = 0; i8 < 8; ++i8)
#pragma unroll
                for (int j = 0; j < 4; ++j)
                    ffma2(acc[i8][j], ad[i8], bd[j]);
        }
    }

    // ---- epilogue ----
    float* Cz = C + (size_t)blockIdx.z * M * Nout;
    bool nfull = (n0 + 64 <= Nout);
#pragma unroll
    for (int i8 = 0; i8 < 8; ++i8) {
        int lm = m0 + ty8 + i8;
        if (lm >= Meff) continue;
        int gr = GATHER ? rows[lm] : lm;
        float v[8];
#pragma unroll
        for (int j = 0; j < 4; ++j) {
            v[2 * j]     = lo2(acc[i8][j]);
            v[2 * j + 1] = hi2(acc[i8][j]);
        }
        int gn0 = n0 + tx8;
        if (epi == EPI_RELU_RES) {
#pragma unroll
            for (int j = 0; j < 8; ++j) {
                float bi = bias[gn0 + j];
                float rv = res[(size_t)gr * Nout + gn0 + j];
                v[j] = fmaxf(v[j] + bi, 0.f) + rv;
            }
        } else if (epi == EPI_BIAS) {
#pragma unroll
            for (int j = 0; j < 8; ++j) v[j] += bias[gn0 + j];
        }
        float* crow = GATHER ? (C + (size_t)gr * Nout) : (Cz + (size_t)lm * Nout);
        if (nfull) {
            *(float4*)(crow + gn0)     = make_float4(v[0], v[1], v[2], v[3]);
            *(float4*)(crow + gn0 + 4) = make_float4(v[4], v[5], v[6], v[7]);
        } else {
#pragma unroll
            for (int j = 0; j < 8; ++j)
                if (gn0 + j < Nout) crow[gn0 + j] = v[j];
        }
    }
}

// ---------------- launch ----------------
extern "C" void kernel_launch(void* const* d_in, const int* in_sizes, int n_in,
                              void* d_out, int out_size) {
    const int*   node_indices = (const int*)d_in[0];
    const int*   edge_index   = (const int*)d_in[1];
    const float* edge_weight  = (const float*)d_in[2];
    const float* partial_emb  = (const float*)d_in[3];
    const float* oov_emb      = (const float*)d_in[4];
    const float* gnn_ln_s     = (const float*)d_in[5];
    const float* gnn_ln_b     = (const float*)d_in[6];
    const float* gnn_w        = (const float*)d_in[7];
    const float* gnn_b        = (const float*)d_in[8];
    const float* post_w       = (const float*)d_in[9];
    const float* post_b       = (const float*)d_in[10];
    const float* pin_w        = (const float*)d_in[11];
    const float* pin_b        = (const float*)d_in[12];
    const float* blk_ln_s     = (const float*)d_in[13];
    const float* blk_ln_b     = (const float*)d_in[14];
    const float* blk_w1       = (const float*)d_in[15];
    const float* blk_b1       = (const float*)d_in[16];
    const float* blk_w2       = (const float*)d_in[17];
    const float* blk_b2       = (const float*)d_in[18];
    const float* pout_w       = (const float*)d_in[19];
    const float* pout_b       = (const float*)d_in[20];
    const float* gene         = (const float*)d_in[21];
    float*       out          = (float*)d_out;

    static float *p_x = nullptr, *p_hln, *p_agg, *p_bw, *p_xg, *p_pert, *p_h, *p_z, *p_t, *p_part, *p_proj, *p_geneT;
    static int   *p_deg, *p_off, *p_cur, *p_bsrc;
    static int   *p_flag2, *p_flag3, *p_list2, *p_list3, *p_cnt2;
    if (!p_x) {
        cudaGetSymbolAddress((void**)&p_x,    g_x);
        cudaGetSymbolAddress((void**)&p_hln,  g_hln);
        cudaGetSymbolAddress((void**)&p_agg,  g_agg);
        cudaGetSymbolAddress((void**)&p_bw,   g_bw);
        cudaGetSymbolAddress((void**)&p_xg,   g_xg);
        cudaGetSymbolAddress((void**)&p_pert, g_pert);
        cudaGetSymbolAddress((void**)&p_h,    g_h);
        cudaGetSymbolAddress((void**)&p_z,    g_z);
        cudaGetSymbolAddress((void**)&p_t,    g_t);
        cudaGetSymbolAddress((void**)&p_part, g_part);
        cudaGetSymbolAddress((void**)&p_proj, g_proj);
        cudaGetSymbolAddress((void**)&p_geneT, g_geneT);
        cudaGetSymbolAddress((void**)&p_deg,  g_deg);
        cudaGetSymbolAddress((void**)&p_off,  g_off);
        cudaGetSymbolAddress((void**)&p_cur,  g_cur);
        cudaGetSymbolAddress((void**)&p_bsrc, g_bsrc);
        cudaGetSymbolAddress((void**)&p_flag2, g_flag2);
        cudaGetSymbolAddress((void**)&p_flag3, g_flag3);
        cudaGetSymbolAddress((void**)&p_list2, g_list2);
        cudaGetSymbolAddress((void**)&p_list3, g_list3);
        cudaGetSymbolAddress((void**)&p_cnt2,  g_cnt2);
    }

    // ---- CSR binning of edges by dst ----
    zero_deg_kernel<<<(NNODE + 255) / 256, 256>>>(p_deg);
    hist_kernel<<<(EDGES + 255) / 256, 256>>>(edge_index, p_deg);
    scan_kernel<<<1, 1024>>>(p_deg, p_off, NNODE);
    copy_cursor_kernel<<<(NNODE + 255) / 256, 256>>>(p_off, p_cur);
    scatter_kernel<<<(EDGES + 255) / 256, 256>>>(edge_index, edge_weight, p_cur, p_bsrc, p_bw);

    // ---- frontier construction ----
    flag_init_kernel<<<(NNODE + 255) / 256, 256>>>(p_flag2, p_flag3, p_cnt2);
    flag_seed_kernel<<<1, BB>>>(node_indices, p_flag2, p_flag3, p_list3);
    flag_edge_kernel<<<(EDGES + 255) / 256, 256>>>(edge_index, p_flag3, p_flag2);
    compact_kernel<<<(NNODE + 255) / 256, 256>>>(p_flag2, p_list2, p_cnt2);

    // ---- gene transpose (padded) ----
    tgene_kernel<<<dim3(NGENE_PAD / 32, RNK / 32), dim3(32, 8)>>>(gene, p_geneT);

    // ---- x = partial_emb (pad rows zero) ----
    copy_x_kernel<<<(NPAD * DG + 255) / 256, 256>>>(partial_emb, p_x);

    // ---- GNN layer 0: dense ----
    ln_kernel<<<NPAD / 8, 256>>>(p_x, gnn_ln_s, gnn_ln_b, p_hln, NPAD, DG, nullptr);
    agg_kernel<<<(NNODE + 7) / 8, 256>>>(p_hln, p_agg, p_off, p_bsrc, p_bw, nullptr);
    gemmp_kernel<false><<<dim3(DG / 64, NPAD / 128, 1), 128>>>(
        p_agg, gnn_w, gnn_b, p_x, p_x, nullptr, nullptr, NPAD, DG, DG, DG, DG, EPI_RELU_RES);

    // ---- GNN layer 1: frontier F2 ----
    ln_kernel<<<NPAD / 8, 256>>>(p_x, gnn_ln_s + DG, gnn_ln_b + DG, p_hln, NPAD, DG, nullptr);
    agg_kernel<<<(NNODE + 7) / 8, 256>>>(p_hln, p_agg, p_off, p_bsrc, p_bw, p_flag2);
    gemmp_kernel<true><<<dim3(DG / 64, (NNODE + 127) / 128, 1), 128>>>(
        p_agg, gnn_w + (size_t)1 * DG * DG, gnn_b + DG, p_x, p_x, p_list2, p_cnt2,
        NNODE, DG, DG, DG, DG, EPI_RELU_RES);

    // ---- GNN layer 2: frontier F3 ----
    ln_kernel<<<NPAD / 8, 256>>>(p_x, gnn_ln_s + 2 * DG, gnn_ln_b + 2 * DG, p_hln, NPAD, DG, p_flag2);
    agg_kernel<<<(NNODE + 7) / 8, 256>>>(p_hln, p_agg, p_off, p_bsrc, p_bw, p_flag3);
    gemmp_kernel<true><<<dim3(DG / 64, BB / 128, 1), 128>>>(
        p_agg, gnn_w + (size_t)2 * DG * DG, gnn_b + 2 * DG, p_x, p_x, p_list3, nullptr,
        BB, DG, DG, DG, DG, EPI_RELU_RES);

    // ---- gather 256 rows, post_mp ----
    gather_kernel<<<BB, DG>>>(p_x, node_indices, p_xg);
    gemmp_kernel<false><<<dim3(DG / 64, BB / 128, 1), 128>>>(
        p_xg, post_w, post_b, nullptr, p_pert, nullptr, nullptr, BB, DG, DG, DG, DG, EPI_BIAS);
    oovfix_kernel<<<BB, DG>>>(node_indices, oov_emb, p_pert);

    // ---- proj_in ----
    gemmp_kernel<false><<<dim3(DH / 64, BB / 128, 1), 128>>>(
        p_pert, pin_w, pin_b, nullptr, p_h, nullptr, nullptr, BB, DH, DH, DG, DG, EPI_BIAS);

    // ---- 6 residual MLP blocks ----
    for (int i = 0; i < 6; ++i) {
        ln_kernel<<<BB / 8, 256>>>(p_h, blk_ln_s + i * DH, blk_ln_b + i * DH, p_z, BB, DH, nullptr);
        gemmp_kernel<false><<<dim3(DI / 64, BB / 128, 4), 128>>>(
            p_z, blk_w1 + (size_t)i * DH * DI, nullptr, nullptr, p_part, nullptr, nullptr,
            BB, DI, DI, DH, DH / 4, EPI_NONE);
        reduce_kernel<<<(BB * DI + 255) / 256, 256>>>(p_t, p_part, blk_b1 + i * DI, 4, BB * DI, DI, 2);
        gemmp_kernel<false><<<dim3(DH / 64, BB / 128, 8), 128>>>(
            p_t, blk_w2 + (size_t)i * DI * DH, nullptr, nullptr, p_part, nullptr, nullptr,
            BB, DH, DH, DI, DI / 8, EPI_NONE);
        reduce_kernel<<<(BB * DH + 255) / 256, 256>>>(p_h, p_part, blk_b2 + i * DH, 8, BB * DH, DH, 1);
    }

    // ---- proj_out (split-K x2) ----
    gemmp_kernel<false><<<dim3((NCLS * RNK) / 64, BB / 128, 2), 128>>>(
        p_h, pout_w, nullptr, nullptr, p_part, nullptr, nullptr,
        BB, NCLS * RNK, NCLS * RNK, DH, DH / 2, EPI_NONE);
    reduce_kernel<<<(BB * NCLS * RNK + 255) / 256, 256>>>(
        p_proj, p_part, pout_b, 2, BB * NCLS * RNK, NCLS * RNK, 0);

    // ---- logits = proj[768,512] @ geneT[512][6656] (output stride 6640) ----
    gemmp_kernel<false><<<dim3(NGENE_PAD / 64, (BB * NCLS) / 128, 1), 128>>>(
        p_proj, p_geneT, nullptr, nullptr, out, nullptr, nullptr,
        BB * NCLS, NGENE_PAD, NGENE, RNK, RNK, EPI_NONE);
}